// round 11
// baseline (speedup 1.0000x reference)
#include <cuda_runtime.h>
#include <cuda_fp16.h>
#include <mma.h>
#include <math.h>
#include <stdint.h>

using namespace nvcuda;

// ---------------- problem constants ----------------
#define T_TOK 4096
#define HIDN  2048
#define NH    16
#define NKV   4
#define HD    128
#define FF    8192
#define BATCH 4
#define SEQ   1024
#define GRP   (NH / NKV)
#define KVW   (NKV * HD)          // 512
#define NQKV  (HIDN + 2 * KVW)    // 3072
#define EPSV  1e-6f
#define SCALE 0.08838834764831845f
#define NEGV  -1000000000.0f

// ---------------- fp32 scratch ----------------
#define OFF_SCORES ((size_t)0)
#define OFF_X2     ((size_t)67108864)
#define OFF_BIAS   ((size_t)75497472)
#define SCRATCH_FLOATS ((size_t)75501568)
__device__ float g_scratch[SCRATCH_FLOATS];

// ---------------- fp16 scratch ----------------
#define HW_QKV   ((size_t)0)
#define HW_O     ((size_t)6291456)
#define HW_G     ((size_t)10485760)
#define HW_U     ((size_t)27262976)
#define HW_D     ((size_t)44040192)
#define H_H16    ((size_t)60817408)
#define H_QKV16  ((size_t)69206016)
#define H_Q16    ((size_t)81788928)
#define H_K16    ((size_t)90177536)
#define H_P16    ((size_t)92274688)
#define H_ATTN16 ((size_t)159383552)
#define H_G16    ((size_t)167772160)
#define HSCRATCH_HALVES ((size_t)201326592)
__device__ __half g_hscratch[HSCRATCH_HALVES];

// ---------------- cp.async helpers ----------------
__device__ __forceinline__ void cp16(uint32_t dst, const void* src) {
    asm volatile("cp.async.cg.shared.global [%0], [%1], 16;" :: "r"(dst), "l"(src));
}
__device__ __forceinline__ void cp_commit() {
    asm volatile("cp.async.commit_group;");
}
template <int N>
__device__ __forceinline__ void cp_wait() {
    asm volatile("cp.async.wait_group %0;" :: "n"(N));
}

typedef wmma::fragment<wmma::matrix_a, 16, 16, 16, __half, wmma::row_major> AFragH;
typedef wmma::fragment<wmma::matrix_b, 16, 16, 16, __half, wmma::col_major> BFragHC;
typedef wmma::fragment<wmma::matrix_b, 16, 16, 16, __half, wmma::row_major> BFragHR;
typedef wmma::fragment<wmma::accumulator, 16, 16, 16, float> CFragH;

// ---------------- shared epilogue helper ----------------
template <int EPI, int HOUT>
__device__ __forceinline__ void epilogue_tile(
    float* stage, CFragH& cf, int lane,
    size_t row_g, size_t col_base,
    void* Cv, int ldc,
    const float* bias, const float* res, const __half* resH)
{
    wmma::store_matrix_sync(stage, cf, 16, wmma::mem_row_major);
    __syncwarp();
    const int r  = lane >> 1;
    const int cq = (lane & 1) << 3;
    const size_t rg = row_g + r;
    const size_t cg = col_base + cq;
    float4 v0 = *(float4*)&stage[r * 16 + cq];
    float4 v1 = *(float4*)&stage[r * 16 + cq + 4];
    if (EPI == 1) {
        float4 b0 = *(const float4*)&bias[cg];
        float4 b1 = *(const float4*)&bias[cg + 4];
        v0.x += b0.x; v0.y += b0.y; v0.z += b0.z; v0.w += b0.w;
        v1.x += b1.x; v1.y += b1.y; v1.z += b1.z; v1.w += b1.w;
    }
    if (EPI == 2) {
        float4 r0 = *(const float4*)&res[rg * ldc + cg];
        float4 r1 = *(const float4*)&res[rg * ldc + cg + 4];
        v0.x += r0.x; v0.y += r0.y; v0.z += r0.z; v0.w += r0.w;
        v1.x += r1.x; v1.y += r1.y; v1.z += r1.z; v1.w += r1.w;
    }
    if (EPI == 3) {
        uint4 gu = *(const uint4*)&resH[rg * ldc + cg];
        __half2* gh = (__half2*)&gu;
        float2 g0 = __half22float2(gh[0]);
        float2 g1 = __half22float2(gh[1]);
        float2 g2 = __half22float2(gh[2]);
        float2 g3 = __half22float2(gh[3]);
        v0.x *= g0.x / (1.f + expf(-g0.x));
        v0.y *= g0.y / (1.f + expf(-g0.y));
        v0.z *= g1.x / (1.f + expf(-g1.x));
        v0.w *= g1.y / (1.f + expf(-g1.y));
        v1.x *= g2.x / (1.f + expf(-g2.x));
        v1.y *= g2.y / (1.f + expf(-g2.y));
        v1.z *= g3.x / (1.f + expf(-g3.x));
        v1.w *= g3.y / (1.f + expf(-g3.y));
    }
    if (HOUT) {
        __half* C = (__half*)Cv;
        __half2 h[4];
        h[0] = __floats2half2_rn(v0.x, v0.y);
        h[1] = __floats2half2_rn(v0.z, v0.w);
        h[2] = __floats2half2_rn(v1.x, v1.y);
        h[3] = __floats2half2_rn(v1.z, v1.w);
        *(uint4*)&C[rg * ldc + cg] = *(uint4*)h;
    } else {
        float* C = (float*)Cv;
        *(float4*)&C[rg * ldc + cg] = v0;
        *(float4*)&C[rg * ldc + cg + 4] = v1;
    }
    __syncwarp();
}

// ============================================================
// casgemm (R9-proven): 128x128 tile, 256 thr, BK=64, 3 stages, 2 CTA/SM
// ============================================================
#define BKC 64
#define CPITCH 72
#define CSTAGE (128 * CPITCH)
#define CAS_SMEM_BYTES (3 * 2 * CSTAGE * 2)   // 110592 B

template <int EPI, int HOUT>
__global__ void __launch_bounds__(256, 2)
casgemm_tn(const __half* __restrict__ A, int lda,
           const __half* __restrict__ B, int ldb,
           void* __restrict__ Cv, int ldc, int K,
           const float* __restrict__ bias,
           const float* __restrict__ res,
           const __half* __restrict__ resH)
{
    extern __shared__ __half csmem[];
    const uint32_t sm32 = (uint32_t)__cvta_generic_to_shared(csmem);

    const int tid  = threadIdx.x;
    const int wid  = tid >> 5;
    const int lane = tid & 31;
    const int m0 = blockIdx.y * 128;
    const int n0 = blockIdx.x * 128;
    const int wm = wid & 1, wn = wid >> 1;

    CFragH c[4][2];
#pragma unroll
    for (int i = 0; i < 4; i++)
#pragma unroll
        for (int j = 0; j < 2; j++) wmma::fill_fragment(c[i][j], 0.f);

    const int row = tid >> 1;
    const int cb  = (tid & 1) << 5;
    const __half* gA = A + (size_t)(m0 + row) * lda + cb;
    const __half* gB = B + (size_t)(n0 + row) * ldb + cb;
    const uint32_t tA = sm32 + (uint32_t)(row * CPITCH + cb) * 2u;
    const uint32_t tB = tA + (uint32_t)CSTAGE * 2u;

#define CAS_LOAD(slot, k0) do {                                         \
        const uint32_t _o = (uint32_t)(slot) * (2u * CSTAGE * 2u);      \
        _Pragma("unroll")                                               \
        for (int _u = 0; _u < 4; _u++) {                                \
            cp16(tA + _o + _u * 16u, gA + (k0) + _u * 8);               \
            cp16(tB + _o + _u * 16u, gB + (k0) + _u * 8);               \
        }                                                               \
    } while (0)

    const int nt = K / BKC;

    CAS_LOAD(0, 0);      cp_commit();
    CAS_LOAD(1, BKC);    cp_commit();

    for (int t = 0; t < nt; t++) {
        cp_wait<1>();
        __syncthreads();
        if (t + 2 < nt) CAS_LOAD((t + 2) % 3, (t + 2) * BKC);
        cp_commit();

        const __half* sA = csmem + (t % 3) * 2 * CSTAGE;
        const __half* sB = sA + CSTAGE;
#pragma unroll
        for (int ks = 0; ks < BKC; ks += 16) {
            AFragH af[4];
            BFragHC bf[2];
#pragma unroll
            for (int i = 0; i < 4; i++)
                wmma::load_matrix_sync(af[i], sA + (wm * 64 + i * 16) * CPITCH + ks, CPITCH);
#pragma unroll
            for (int j = 0; j < 2; j++)
                wmma::load_matrix_sync(bf[j], sB + (wn * 32 + j * 16) * CPITCH + ks, CPITCH);
#pragma unroll
            for (int i = 0; i < 4; i++)
#pragma unroll
                for (int j = 0; j < 2; j++)
                    wmma::mma_sync(c[i][j], af[i], bf[j], c[i][j]);
        }
    }
    __syncthreads();

    float* stage = reinterpret_cast<float*>(csmem) + wid * 256;
#pragma unroll
    for (int i = 0; i < 4; i++)
#pragma unroll
        for (int j = 0; j < 2; j++)
            epilogue_tile<EPI, HOUT>(stage, c[i][j], lane,
                (size_t)(m0 + wm * 64 + i * 16),
                (size_t)(n0 + wn * 32 + j * 16),
                Cv, ldc, bias, res, resH);
#undef CAS_LOAD
}

// ============================================================
// casgemm2: 128x256 tile, 256 thr, warp tile 64x64 (c[4][4]),
// BK=64, 3 stages, 1 CTA/SM.  For the big MLP GEMMs.
// ============================================================
#define C2PITCH 72
#define C2ASTAGE (128 * C2PITCH)        // 9216 halves
#define C2BSTAGE (256 * C2PITCH)        // 18432 halves
#define C2SLOT   (C2ASTAGE + C2BSTAGE)  // 27648 halves
#define CAS2_SMEM_BYTES (3 * C2SLOT * 2)  // 165888 B

template <int EPI, int HOUT>
__global__ void __launch_bounds__(256, 1)
casgemm2_tn(const __half* __restrict__ A, int lda,
            const __half* __restrict__ B, int ldb,
            void* __restrict__ Cv, int ldc, int K,
            const float* __restrict__ bias,
            const float* __restrict__ res,
            const __half* __restrict__ resH)
{
    extern __shared__ __half csmem[];
    const uint32_t sm32 = (uint32_t)__cvta_generic_to_shared(csmem);

    const int tid  = threadIdx.x;
    const int wid  = tid >> 5;
    const int lane = tid & 31;
    const int m0 = blockIdx.y * 128;
    const int n0 = blockIdx.x * 256;
    const int wm = wid & 1;      // 2 row slabs of 64
    const int wn = wid >> 1;     // 4 col slabs of 64

    CFragH c[4][4];
#pragma unroll
    for (int i = 0; i < 4; i++)
#pragma unroll
        for (int j = 0; j < 4; j++) wmma::fill_fragment(c[i][j], 0.f);

    const int row = tid >> 1;           // 0..127
    const int cb  = (tid & 1) << 5;     // 0 or 32
    const __half* gA  = A + (size_t)(m0 + row) * lda + cb;
    const __half* gB0 = B + (size_t)(n0 + row) * ldb + cb;
    const __half* gB1 = gB0 + (size_t)128 * ldb;
    const uint32_t tA  = sm32 + (uint32_t)(row * C2PITCH + cb) * 2u;
    const uint32_t tB0 = sm32 + (uint32_t)(C2ASTAGE + row * C2PITCH + cb) * 2u;
    const uint32_t tB1 = tB0 + (uint32_t)(128 * C2PITCH) * 2u;

#define CAS2_LOAD(slot, k0) do {                                        \
        const uint32_t _o = (uint32_t)(slot) * (C2SLOT * 2u);           \
        _Pragma("unroll")                                               \
        for (int _u = 0; _u < 4; _u++) {                                \
            cp16(tA  + _o + _u * 16u, gA  + (k0) + _u * 8);             \
            cp16(tB0 + _o + _u * 16u, gB0 + (k0) + _u * 8);             \
            cp16(tB1 + _o + _u * 16u, gB1 + (k0) + _u * 8);             \
        }                                                               \
    } while (0)

    const int nt = K / BKC;

    CAS2_LOAD(0, 0);      cp_commit();
    CAS2_LOAD(1, BKC);    cp_commit();

    for (int t = 0; t < nt; t++) {
        cp_wait<1>();
        __syncthreads();
        if (t + 2 < nt) CAS2_LOAD((t + 2) % 3, (t + 2) * BKC);
        cp_commit();

        const __half* sA = csmem + (t % 3) * C2SLOT;
        const __half* sB = sA + C2ASTAGE;
#pragma unroll
        for (int ks = 0; ks < BKC; ks += 16) {
            AFragH af[4];
            BFragHC bf[4];
#pragma unroll
            for (int i = 0; i < 4; i++)
                wmma::load_matrix_sync(af[i], sA + (wm * 64 + i * 16) * C2PITCH + ks, C2PITCH);
#pragma unroll
            for (int j = 0; j < 4; j++)
                wmma::load_matrix_sync(bf[j], sB + (wn * 64 + j * 16) * C2PITCH + ks, C2PITCH);
#pragma unroll
            for (int i = 0; i < 4; i++)
#pragma unroll
                for (int j = 0; j < 4; j++)
                    wmma::mma_sync(c[i][j], af[i], bf[j], c[i][j]);
        }
    }
    __syncthreads();

    float* stage = reinterpret_cast<float*>(csmem) + wid * 256;
#pragma unroll
    for (int i = 0; i < 4; i++)
#pragma unroll
        for (int j = 0; j < 4; j++)
            epilogue_tile<EPI, HOUT>(stage, c[i][j], lane,
                (size_t)(m0 + wm * 64 + i * 16),
                (size_t)(n0 + wn * 64 + j * 16),
                Cv, ldc, bias, res, resH);
#undef CAS2_LOAD
}

// ============================================================
// PV cp.async (R10-proven)
// ============================================================
#define PV_APITCH 72
#define PV_ASTAGE (128 * PV_APITCH)
#define PV_BPITCH 136
#define PV_BSTAGE (64 * PV_BPITCH)
#define PV_SLOT   (PV_ASTAGE + PV_BSTAGE)
#define PV_SMEM_BYTES (3 * PV_SLOT * 2)

__global__ void __launch_bounds__(256, 2)
hpv_cas(const __half* __restrict__ p, const __half* __restrict__ v, int ldv,
        __half* __restrict__ out)
{
    extern __shared__ __half csmem[];
    const uint32_t sm32 = (uint32_t)__cvta_generic_to_shared(csmem);

    const int z = blockIdx.z;
    const int b = z / NH, h = z % NH, kvh = h / GRP;
    const int m0 = blockIdx.y * 128;
    const __half* A = p + (size_t)z * SEQ * SEQ;
    const __half* B = v + (size_t)b * SEQ * ldv + (size_t)kvh * HD;
    __half* C = out + (size_t)b * SEQ * HIDN + (size_t)h * HD;

    const int tid  = threadIdx.x;
    const int wid  = tid >> 5;
    const int lane = tid & 31;
    const int wm = wid & 1, wn = wid >> 1;

    CFragH c[4][2];
#pragma unroll
    for (int i = 0; i < 4; i++)
#pragma unroll
        for (int j = 0; j < 2; j++) wmma::fill_fragment(c[i][j], 0.f);

    const int arow = tid >> 1;
    const int acb  = (tid & 1) << 5;
    const int brow = tid >> 2;
    const int bcb  = (tid & 3) << 5;
    const __half* gA = A + (size_t)(m0 + arow) * SEQ + acb;
    const uint32_t tA = sm32 + (uint32_t)(arow * PV_APITCH + acb) * 2u;
    const uint32_t tB = sm32 + (uint32_t)(PV_ASTAGE + brow * PV_BPITCH + bcb) * 2u;

#define PV_LOAD(slot, k0) do {                                          \
        const uint32_t _o = (uint32_t)(slot) * (PV_SLOT * 2u);          \
        const __half* _gb = B + (size_t)((k0) + brow) * ldv + bcb;      \
        _Pragma("unroll")                                               \
        for (int _u = 0; _u < 4; _u++) {                                \
            cp16(tA + _o + _u * 16u, gA + (k0) + _u * 8);               \
            cp16(tB + _o + _u * 16u, _gb + _u * 8);                     \
        }                                                               \
    } while (0)

    const int nt = (m0 + 128) / BKC;

    PV_LOAD(0, 0);    cp_commit();
    PV_LOAD(1, BKC);  cp_commit();

    for (int t = 0; t < nt; t++) {
        cp_wait<1>();
        __syncthreads();
        if (t + 2 < nt) PV_LOAD((t + 2) % 3, (t + 2) * BKC);
        cp_commit();

        const __half* sA = csmem + (t % 3) * PV_SLOT;
        const __half* sB = sA + PV_ASTAGE;
#pragma unroll
        for (int ks = 0; ks < BKC; ks += 16) {
            AFragH af[4];
            BFragHR bf[2];
#pragma unroll
            for (int i = 0; i < 4; i++)
                wmma::load_matrix_sync(af[i], sA + (wm * 64 + i * 16) * PV_APITCH + ks, PV_APITCH);
#pragma unroll
            for (int j = 0; j < 2; j++)
                wmma::load_matrix_sync(bf[j], sB + ks * PV_BPITCH + (wn * 32 + j * 16), PV_BPITCH);
#pragma unroll
            for (int i = 0; i < 4; i++)
#pragma unroll
                for (int j = 0; j < 2; j++)
                    wmma::mma_sync(c[i][j], af[i], bf[j], c[i][j]);
        }
    }
    __syncthreads();

    float* stage = reinterpret_cast<float*>(csmem) + wid * 256;
    const int r  = lane >> 1;
    const int cq = (lane & 1) << 3;
#pragma unroll
    for (int i = 0; i < 4; i++) {
#pragma unroll
        for (int j = 0; j < 2; j++) {
            wmma::store_matrix_sync(stage, c[i][j], 16, wmma::mem_row_major);
            __syncwarp();
            const size_t row_g = (size_t)(m0 + wm * 64 + i * 16 + r);
            const size_t col_g = (size_t)(wn * 32 + j * 16 + cq);
            float4 v0 = *(float4*)&stage[r * 16 + cq];
            float4 v1 = *(float4*)&stage[r * 16 + cq + 4];
            __half2 hh[4];
            hh[0] = __floats2half2_rn(v0.x, v0.y);
            hh[1] = __floats2half2_rn(v0.z, v0.w);
            hh[2] = __floats2half2_rn(v1.x, v1.y);
            hh[3] = __floats2half2_rn(v1.z, v1.w);
            *(uint4*)&C[row_g * HIDN + col_g] = *(uint4*)hh;
            __syncwarp();
        }
    }
#undef PV_LOAD
}

// ============================================================
// Scores (R10-proven): q16(prescaled).k16 + analytic mask
// ============================================================
#define BM 128
#define BN 128
#define BK 32
#define HPITCH 40
#define HSTAGE (128 * HPITCH)

__global__ void __launch_bounds__(256, 2)
hscores(const __half* __restrict__ q, const __half* __restrict__ k,
        float* __restrict__ scores)
{
    if (blockIdx.x > blockIdx.y) return;

    const int z = blockIdx.z;
    const int b = z / NH, h = z % NH, kvh = h / GRP;
    const int m0 = blockIdx.y * BM;
    const int n0 = blockIdx.x * BN;
    const __half* A = q + (size_t)b * SEQ * HIDN + (size_t)h * HD;
    const __half* B = k + (size_t)b * SEQ * KVW + (size_t)kvh * HD;
    float* C = scores + (size_t)z * SEQ * SEQ;
    const bool diag = (blockIdx.x == blockIdx.y);

    __shared__ __align__(16) __half smem[4 * HSTAGE];
    __half* sA[2] = { smem,              smem + HSTAGE };
    __half* sB[2] = { smem + 2 * HSTAGE, smem + 3 * HSTAGE };

    const int tid  = threadIdx.x;
    const int wid  = tid >> 5;
    const int lane = tid & 31;
    const int wm = wid & 1, wn = wid >> 1;

    CFragH c[4][2];
#pragma unroll
    for (int i = 0; i < 4; i++)
#pragma unroll
        for (int jj = 0; jj < 2; jj++) wmma::fill_fragment(c[i][jj], 0.f);

    const int row = tid >> 1;
    const int c0  = (tid & 1) << 4;
    const __half* gA = A + (size_t)(m0 + row) * HIDN + c0;
    const __half* gB = B + (size_t)(n0 + row) * KVW + c0;

    uint4 ra0, ra1, rb0, rb1;
    ra0 = *(const uint4*)(gA);
    ra1 = *(const uint4*)(gA + 8);
    rb0 = *(const uint4*)(gB);
    rb1 = *(const uint4*)(gB + 8);
    {
        __half* a = sA[0] + row * HPITCH + c0;
        *(uint4*)a = ra0; *(uint4*)(a + 8) = ra1;
        __half* bb = sB[0] + row * HPITCH + c0;
        *(uint4*)bb = rb0; *(uint4*)(bb + 8) = rb1;
    }
    __syncthreads();

    const int nt = HD / BK;
    for (int t = 0; t < nt; t++) {
        const int cur = t & 1;
        if (t + 1 < nt) {
            const int k0 = (t + 1) * BK;
            ra0 = *(const uint4*)(gA + k0);
            ra1 = *(const uint4*)(gA + k0 + 8);
            rb0 = *(const uint4*)(gB + k0);
            rb1 = *(const uint4*)(gB + k0 + 8);
        }
#pragma unroll
        for (int ks = 0; ks < BK; ks += 16) {
            AFragH af[4];
            BFragHC bf[2];
#pragma unroll
            for (int i = 0; i < 4; i++)
                wmma::load_matrix_sync(af[i], sA[cur] + (wm * 64 + i * 16) * HPITCH + ks, HPITCH);
#pragma unroll
            for (int jj = 0; jj < 2; jj++)
                wmma::load_matrix_sync(bf[jj], sB[cur] + (wn * 32 + jj * 16) * HPITCH + ks, HPITCH);
#pragma unroll
            for (int i = 0; i < 4; i++)
#pragma unroll
                for (int jj = 0; jj < 2; jj++)
                    wmma::mma_sync(c[i][jj], af[i], bf[jj], c[i][jj]);
        }
        if (t + 1 < nt) {
            const int nxt = cur ^ 1;
            __half* a = sA[nxt] + row * HPITCH + c0;
            *(uint4*)a = ra0; *(uint4*)(a + 8) = ra1;
            __half* bb = sB[nxt] + row * HPITCH + c0;
            *(uint4*)bb = rb0; *(uint4*)(bb + 8) = rb1;
        }
        __syncthreads();
    }

    float* stage = reinterpret_cast<float*>(smem) + wid * 256;
    const int r  = lane >> 1;
    const int cq = (lane & 1) << 3;
#pragma unroll
    for (int i = 0; i < 4; i++) {
#pragma unroll
        for (int jj = 0; jj < 2; jj++) {
            wmma::store_matrix_sync(stage, c[i][jj], 16, wmma::mem_row_major);
            __syncwarp();
            const size_t row_g = (size_t)(m0 + wm * 64 + i * 16 + r);
            const size_t col_g = (size_t)(n0 + wn * 32 + jj * 16 + cq);
            float4 v0 = *(float4*)&stage[r * 16 + cq];
            float4 v1 = *(float4*)&stage[r * 16 + cq + 4];
            if (diag) {
                if (col_g + 0 > row_g) v0.x += NEGV;
                if (col_g + 1 > row_g) v0.y += NEGV;
                if (col_g + 2 > row_g) v0.z += NEGV;
                if (col_g + 3 > row_g) v0.w += NEGV;
                if (col_g + 4 > row_g) v1.x += NEGV;
                if (col_g + 5 > row_g) v1.y += NEGV;
                if (col_g + 6 > row_g) v1.z += NEGV;
                if (col_g + 7 > row_g) v1.w += NEGV;
            }
            *(float4*)&C[row_g * SEQ + col_g] = v0;
            *(float4*)&C[row_g * SEQ + col_g + 4] = v1;
            __syncwarp();
        }
    }
}

// ---------------- elementwise / reduction kernels ----------------

__global__ void __launch_bounds__(256)
f2h_kernel(const float* __restrict__ in, __half* __restrict__ out, int n)
{
    int i = (blockIdx.x * blockDim.x + threadIdx.x) * 4;
    int stride = gridDim.x * blockDim.x * 4;
    for (; i < n; i += stride) {
        float4 v = *(const float4*)(in + i);
        ((__half2*)(out + i))[0] = __floats2half2_rn(v.x, v.y);
        ((__half2*)(out + i))[1] = __floats2half2_rn(v.z, v.w);
    }
}

__global__ void __launch_bounds__(256)
bias_concat_kernel(const float* __restrict__ bq, const float* __restrict__ bk,
                   const float* __restrict__ bv, float* __restrict__ dst)
{
    int i = blockIdx.x * blockDim.x + threadIdx.x;
    if (i < HIDN) dst[i] = bq[i];
    else if (i < HIDN + KVW) dst[i] = bk[i - HIDN];
    else if (i < NQKV) dst[i] = bv[i - HIDN - KVW];
}

__global__ void __launch_bounds__(256)
softmax_kernel(const float* __restrict__ s, __half* __restrict__ p16)
{
    const size_t base = (size_t)blockIdx.x * SEQ;
    const int r = blockIdx.x & (SEQ - 1);
    const int L = ((r >> 7) + 1) << 7;
    const int tid = threadIdx.x;
    __shared__ float red[8];

    float vals[4];
    float mx = -1e30f;
    int cnt = 0;
    for (int idx = tid; idx < L; idx += 256) {
        vals[cnt] = s[base + idx];
        mx = fmaxf(mx, vals[cnt]);
        cnt++;
    }
#pragma unroll
    for (int o = 16; o > 0; o >>= 1) mx = fmaxf(mx, __shfl_xor_sync(0xffffffffu, mx, o));
    if ((tid & 31) == 0) red[tid >> 5] = mx;
    __syncthreads();
    float m2 = fmaxf(fmaxf(fmaxf(red[0], red[1]), fmaxf(red[2], red[3])),
                     fmaxf(fmaxf(red[4], red[5]), fmaxf(red[6], red[7])));
    __syncthreads();

    float sum = 0.f;
    for (int c = 0; c < cnt; c++) {
        vals[c] = expf(vals[c] - m2);
        sum += vals[c];
    }
#pragma unroll
    for (int o = 16; o > 0; o >>= 1) sum += __shfl_xor_sync(0xffffffffu, sum, o);
    if ((tid & 31) == 0) red[tid >> 5] = sum;
    __syncthreads();
    float tot = red[0] + red[1] + red[2] + red[3] + red[4] + red[5] + red[6] + red[7];
    float inv = 1.f / tot;
    int c = 0;
    for (int idx = tid; idx < L; idx += 256, c++)
        p16[base + idx] = __float2half_rn(vals[c] * inv);
}

__global__ void __launch_bounds__(256)
rmsnorm_h_kernel(const float* __restrict__ x, const float* __restrict__ w,
                 __half* __restrict__ out)
{
    const size_t base = (size_t)blockIdx.x * HIDN;
    const int tid = threadIdx.x;
    __shared__ float red[8];

    float v[8];
    float ss = 0.f;
#pragma unroll
    for (int jj = 0; jj < 8; jj++) {
        v[jj] = x[base + tid + jj * 256];
        ss += v[jj] * v[jj];
    }
#pragma unroll
    for (int o = 16; o > 0; o >>= 1) ss += __shfl_xor_sync(0xffffffffu, ss, o);
    if ((tid & 31) == 0) red[tid >> 5] = ss;
    __syncthreads();
    float tot = red[0] + red[1] + red[2] + red[3] + red[4] + red[5] + red[6] + red[7];
    float r = rsqrtf(tot * (1.f / HIDN) + EPSV);
#pragma unroll
    for (int jj = 0; jj < 8; jj++)
        out[base + tid + jj * 256] = __float2half_rn(v[jj] * r * w[tid + jj * 256]);
}

__global__ void __launch_bounds__(128)
head_rms_rope_h_kernel(const __half* __restrict__ buf, int instride, int inoff,
                       const float* __restrict__ w,
                       const float* __restrict__ cs, const float* __restrict__ sn,
                       __half* __restrict__ out16, int outstride, float outscale)
{
    const int t = blockIdx.x;
    const int h = blockIdx.y;
    const int i = threadIdx.x;
    const size_t iidx = (size_t)t * instride + inoff + h * HD + i;
    const size_t oidx = (size_t)t * outstride + h * HD + i;

    float v = __half2float(buf[iidx]);
    float ss = v * v;
#pragma unroll
    for (int o = 16; o > 0; o >>= 1) ss += __shfl_xor_sync(0xffffffffu, ss, o);
    __shared__ float red[4];
    if ((i & 31) == 0) red[i >> 5] = ss;
    __syncthreads();
    float tot = red[0] + red[1] + red[2] + red[3];
    float n = v * rsqrtf(tot * (1.f / HD) + EPSV) * w[i];

    __shared__ float sm[HD];
    sm[i] = n;
    __syncthreads();
    float rot = (i < 64) ? -sm[i + 64] : sm[i - 64];
    float r = (n * cs[(size_t)t * HD + i] + rot * sn[(size_t)t * HD + i]) * outscale;
    out16[oidx] = __float2half_rn(r);
}

extern "C" void kernel_launch(void* const* d_in, const int* in_sizes, int n_in,
                              void* d_out, int out_size)
{
    const float* x    = (const float*)d_in[0];
    const float* cosv = (const float*)d_in[1];
    const float* sinv = (const float*)d_in[2];
    const float* wq   = (const float*)d_in[4];
    const float* bq   = (const float*)d_in[5];
    const float* wk   = (const float*)d_in[6];
    const float* bk   = (const float*)d_in[7];
    const float* wv   = (const float*)d_in[8];
    const float* bv   = (const float*)d_in[9];
    const float* wo   = (const float*)d_in[10];
    const float* qw   = (const float*)d_in[11];
    const float* kw   = (const float*)d_in[12];
    const float* ln1  = (const float*)d_in[13];
    const float* ln2  = (const float*)d_in[14];
    const float* wg   = (const float*)d_in[15];
    const float* wu   = (const float*)d_in[16];
    const float* wd   = (const float*)d_in[17];
    float* out = (float*)d_out;

    float* s = nullptr;
    cudaGetSymbolAddress((void**)&s, g_scratch);
    __half* hs = nullptr;
    cudaGetSymbolAddress((void**)&hs, g_hscratch);

    float* scores = s + OFF_SCORES;
    float* x2     = s + OFF_X2;
    float* biasc  = s + OFF_BIAS;

    __half* hwqkv  = hs + HW_QKV;
    __half* hwo    = hs + HW_O;
    __half* hwg    = hs + HW_G;
    __half* hwu    = hs + HW_U;
    __half* hwd    = hs + HW_D;
    __half* h16    = hs + H_H16;
    __half* qkv16  = hs + H_QKV16;
    __half* q16    = hs + H_Q16;
    __half* k16    = hs + H_K16;
    __half* p16    = hs + H_P16;
    __half* at16   = hs + H_ATTN16;
    __half* g16    = hs + H_G16;

    cudaFuncSetAttribute(casgemm_tn<1, 1>,  cudaFuncAttributeMaxDynamicSharedMemorySize, CAS_SMEM_BYTES);
    cudaFuncSetAttribute(casgemm_tn<2, 0>,  cudaFuncAttributeMaxDynamicSharedMemorySize, CAS_SMEM_BYTES);
    cudaFuncSetAttribute(casgemm2_tn<0, 1>, cudaFuncAttributeMaxDynamicSharedMemorySize, CAS2_SMEM_BYTES);
    cudaFuncSetAttribute(casgemm2_tn<3, 1>, cudaFuncAttributeMaxDynamicSharedMemorySize, CAS2_SMEM_BYTES);
    cudaFuncSetAttribute(casgemm2_tn<2, 0>, cudaFuncAttributeMaxDynamicSharedMemorySize, CAS2_SMEM_BYTES);
    cudaFuncSetAttribute(hpv_cas,           cudaFuncAttributeMaxDynamicSharedMemorySize, PV_SMEM_BYTES);

    // 0. weights fp32 -> fp16 (QKV concatenated)
    f2h_kernel<<<2048, 256>>>(wq, hwqkv,                       HIDN * HIDN);
    f2h_kernel<<<1024, 256>>>(wk, hwqkv + HIDN * HIDN,         KVW * HIDN);
    f2h_kernel<<<1024, 256>>>(wv, hwqkv + (HIDN + KVW) * HIDN, KVW * HIDN);
    f2h_kernel<<<2048, 256>>>(wo, hwo, HIDN * HIDN);
    f2h_kernel<<<4096, 256>>>(wg, hwg, FF * HIDN);
    f2h_kernel<<<4096, 256>>>(wu, hwu, FF * HIDN);
    f2h_kernel<<<4096, 256>>>(wd, hwd, HIDN * FF);
    bias_concat_kernel<<<12, 256>>>(bq, bk, bv, biasc);

    // 1. h16 = rmsnorm(x, ln1)
    rmsnorm_h_kernel<<<T_TOK, 256>>>(x, ln1, h16);

    // 2. fused QKV projection (+bias) -> fp16 qkv16
    casgemm_tn<1, 1><<<dim3(NQKV / 128, T_TOK / 128), 256, CAS_SMEM_BYTES>>>(
        h16, HIDN, hwqkv, HIDN, qkv16, NQKV, HIDN, biasc, nullptr, nullptr);

    // 3-4. per-head RMS + RoPE -> q16 (pre-scaled) / k16 ; V stays in qkv16
    head_rms_rope_h_kernel<<<dim3(T_TOK, NH),  HD>>>(qkv16, NQKV, 0,    qw, cosv, sinv, q16, HIDN, SCALE);
    head_rms_rope_h_kernel<<<dim3(T_TOK, NKV), HD>>>(qkv16, NQKV, HIDN, kw, cosv, sinv, k16, KVW, 1.0f);

    // 5. scores (lower triangle, analytic mask)
    hscores<<<dim3(SEQ / BN, SEQ / BM, BATCH * NH), 256>>>(q16, k16, scores);

    // 6. softmax -> p16
    softmax_kernel<<<BATCH * NH * SEQ, 256>>>(scores, p16);

    // 7. attn16 = P @ V (cp.async; V in-place in qkv16)
    hpv_cas<<<dim3(1, SEQ / 128, BATCH * NH), 256, PV_SMEM_BYTES>>>(
        p16, qkv16 + HIDN + KVW, NQKV, at16);

    // 8. x2 = x + attn @ wo^T
    casgemm_tn<2, 0><<<dim3(HIDN / 128, T_TOK / 128), 256, CAS_SMEM_BYTES>>>(
        at16, HIDN, hwo, HIDN, x2, HIDN, HIDN, nullptr, x, nullptr);

    // 9. h16 = rmsnorm(x2, ln2)
    rmsnorm_h_kernel<<<T_TOK, 256>>>(x2, ln2, h16);

    // 10. gate -> g16 (fp16), wide tile
    casgemm2_tn<0, 1><<<dim3(FF / 256, T_TOK / 128), 256, CAS2_SMEM_BYTES>>>(
        h16, HIDN, hwg, HIDN, g16, FF, HIDN, nullptr, nullptr, nullptr);

    // 11. up + fused silu: g16 = silu(g16) * up (in place), wide tile
    casgemm2_tn<3, 1><<<dim3(FF / 256, T_TOK / 128), 256, CAS2_SMEM_BYTES>>>(
        h16, HIDN, hwu, HIDN, g16, FF, HIDN, nullptr, nullptr, g16);

    // 12. out = x2 + g16 @ wd^T, wide tile
    casgemm2_tn<2, 0><<<dim3(HIDN / 256, T_TOK / 128), 256, CAS2_SMEM_BYTES>>>(
        g16, FF, hwd, FF, out, HIDN, FF, nullptr, x2, nullptr);
}

// round 12
// speedup vs baseline: 1.0213x; 1.0213x over previous
#include <cuda_runtime.h>
#include <cuda_fp16.h>
#include <mma.h>
#include <math.h>
#include <stdint.h>

using namespace nvcuda;

// ---------------- problem constants ----------------
#define T_TOK 4096
#define HIDN  2048
#define NH    16
#define NKV   4
#define HD    128
#define FF    8192
#define BATCH 4
#define SEQ   1024
#define GRP   (NH / NKV)
#define KVW   (NKV * HD)          // 512
#define NQKV  (HIDN + 2 * KVW)    // 3072
#define EPSV  1e-6f
#define SCALE 0.08838834764831845f
#define NEGV  -1000000000.0f

// ---------------- fp32 scratch ----------------
#define OFF_SCORES ((size_t)0)
#define OFF_X2     ((size_t)67108864)
#define OFF_BIAS   ((size_t)75497472)
#define SCRATCH_FLOATS ((size_t)75501568)
__device__ float g_scratch[SCRATCH_FLOATS];

// ---------------- fp16 scratch ----------------
#define HW_QKV   ((size_t)0)
#define HW_O     ((size_t)6291456)
#define HW_G     ((size_t)10485760)
#define HW_U     ((size_t)27262976)
#define HW_D     ((size_t)44040192)
#define H_H16    ((size_t)60817408)
#define H_QKV16  ((size_t)69206016)
#define H_Q16    ((size_t)81788928)
#define H_K16    ((size_t)90177536)
#define H_P16    ((size_t)92274688)
#define H_ATTN16 ((size_t)159383552)
#define H_G16    ((size_t)167772160)
#define HSCRATCH_HALVES ((size_t)201326592)
__device__ __half g_hscratch[HSCRATCH_HALVES];

// ---------------- fast exp (FMA/ALU pipes, no MUFU) ----------------
// exp(x) = 2^(x*log2e); 2^f via degree-6 Taylor (rel err <= ~2e-5)
__device__ __forceinline__ float fast_exp(float x)
{
    float t = x * 1.442695041f;
    t = fminf(fmaxf(t, -126.f), 126.f);
    float fi = floorf(t);
    float f = t - fi;
    float p = 1.f + f * (0.69314718056f + f * (0.24022650696f + f * (0.05550410866f
              + f * (0.00961812911f + f * (0.00133335581f + f * 0.00015403530f)))));
    return __int_as_float(((int)fi + 127) << 23) * p;
}

// ---------------- cp.async helpers ----------------
__device__ __forceinline__ void cp16(uint32_t dst, const void* src) {
    asm volatile("cp.async.cg.shared.global [%0], [%1], 16;" :: "r"(dst), "l"(src));
}
__device__ __forceinline__ void cp_commit() {
    asm volatile("cp.async.commit_group;");
}
template <int N>
__device__ __forceinline__ void cp_wait() {
    asm volatile("cp.async.wait_group %0;" :: "n"(N));
}

typedef wmma::fragment<wmma::matrix_a, 16, 16, 16, __half, wmma::row_major> AFragH;
typedef wmma::fragment<wmma::matrix_b, 16, 16, 16, __half, wmma::col_major> BFragHC;
typedef wmma::fragment<wmma::matrix_b, 16, 16, 16, __half, wmma::row_major> BFragHR;
typedef wmma::fragment<wmma::accumulator, 16, 16, 16, float> CFragH;

// ============================================================
// casgemm (R9/R10-proven): 128x128 tile, 256 thr, BK=64,
// 3 stages, 2 CTA/SM.  C[M,N] = A[M,K] @ B[N,K]^T.
// EPI: 0 none, 1 +bias, 2 +res(fp32), 3 silu(resH)*acc.
// HOUT: 0 fp32 C, 1 fp16 C.
// ============================================================
#define BKC 64
#define CPITCH 72
#define CSTAGE (128 * CPITCH)
#define CAS_SMEM_BYTES (3 * 2 * CSTAGE * 2)   // 110592 B

template <int EPI, int HOUT>
__global__ void __launch_bounds__(256, 2)
casgemm_tn(const __half* __restrict__ A, int lda,
           const __half* __restrict__ B, int ldb,
           void* __restrict__ Cv, int ldc, int K,
           const float* __restrict__ bias,
           const float* __restrict__ res,
           const __half* __restrict__ resH)
{
    extern __shared__ __half csmem[];
    const uint32_t sm32 = (uint32_t)__cvta_generic_to_shared(csmem);

    const int tid  = threadIdx.x;
    const int wid  = tid >> 5;
    const int lane = tid & 31;
    const int m0 = blockIdx.y * 128;
    const int n0 = blockIdx.x * 128;
    const int wm = wid & 1, wn = wid >> 1;

    CFragH c[4][2];
#pragma unroll
    for (int i = 0; i < 4; i++)
#pragma unroll
        for (int j = 0; j < 2; j++) wmma::fill_fragment(c[i][j], 0.f);

    const int row = tid >> 1;
    const int cb  = (tid & 1) << 5;
    const __half* gA = A + (size_t)(m0 + row) * lda + cb;
    const __half* gB = B + (size_t)(n0 + row) * ldb + cb;
    const uint32_t tA = sm32 + (uint32_t)(row * CPITCH + cb) * 2u;
    const uint32_t tB = tA + (uint32_t)CSTAGE * 2u;

#define CAS_LOAD(slot, k0) do {                                         \
        const uint32_t _o = (uint32_t)(slot) * (2u * CSTAGE * 2u);      \
        _Pragma("unroll")                                               \
        for (int _u = 0; _u < 4; _u++) {                                \
            cp16(tA + _o + _u * 16u, gA + (k0) + _u * 8);               \
            cp16(tB + _o + _u * 16u, gB + (k0) + _u * 8);               \
        }                                                               \
    } while (0)

    const int nt = K / BKC;

    CAS_LOAD(0, 0);      cp_commit();
    CAS_LOAD(1, BKC);    cp_commit();

    for (int t = 0; t < nt; t++) {
        cp_wait<1>();
        __syncthreads();
        if (t + 2 < nt) CAS_LOAD((t + 2) % 3, (t + 2) * BKC);
        cp_commit();

        const __half* sA = csmem + (t % 3) * 2 * CSTAGE;
        const __half* sB = sA + CSTAGE;
#pragma unroll
        for (int ks = 0; ks < BKC; ks += 16) {
            AFragH af[4];
            BFragHC bf[2];
#pragma unroll
            for (int i = 0; i < 4; i++)
                wmma::load_matrix_sync(af[i], sA + (wm * 64 + i * 16) * CPITCH + ks, CPITCH);
#pragma unroll
            for (int j = 0; j < 2; j++)
                wmma::load_matrix_sync(bf[j], sB + (wn * 32 + j * 16) * CPITCH + ks, CPITCH);
#pragma unroll
            for (int i = 0; i < 4; i++)
#pragma unroll
                for (int j = 0; j < 2; j++)
                    wmma::mma_sync(c[i][j], af[i], bf[j], c[i][j]);
        }
    }
    __syncthreads();

    float* stage = reinterpret_cast<float*>(csmem) + wid * 256;
    const int r  = lane >> 1;
    const int cq = (lane & 1) << 3;
#pragma unroll
    for (int i = 0; i < 4; i++) {
#pragma unroll
        for (int j = 0; j < 2; j++) {
            wmma::store_matrix_sync(stage, c[i][j], 16, wmma::mem_row_major);
            __syncwarp();
            const size_t row_g = (size_t)(m0 + wm * 64 + i * 16 + r);
            const size_t col_g = (size_t)(n0 + wn * 32 + j * 16 + cq);
            float4 v0 = *(float4*)&stage[r * 16 + cq];
            float4 v1 = *(float4*)&stage[r * 16 + cq + 4];
            if (EPI == 1) {
                float4 b0 = *(const float4*)&bias[col_g];
                float4 b1 = *(const float4*)&bias[col_g + 4];
                v0.x += b0.x; v0.y += b0.y; v0.z += b0.z; v0.w += b0.w;
                v1.x += b1.x; v1.y += b1.y; v1.z += b1.z; v1.w += b1.w;
            }
            if (EPI == 2) {
                float4 r0 = *(const float4*)&res[row_g * ldc + col_g];
                float4 r1 = *(const float4*)&res[row_g * ldc + col_g + 4];
                v0.x += r0.x; v0.y += r0.y; v0.z += r0.z; v0.w += r0.w;
                v1.x += r1.x; v1.y += r1.y; v1.z += r1.z; v1.w += r1.w;
            }
            if (EPI == 3) {
                uint4 gu = *(const uint4*)&resH[row_g * ldc + col_g];
                __half2* gh = (__half2*)&gu;
                float2 g0 = __half22float2(gh[0]);
                float2 g1 = __half22float2(gh[1]);
                float2 g2 = __half22float2(gh[2]);
                float2 g3 = __half22float2(gh[3]);
                v0.x *= g0.x / (1.f + fast_exp(-g0.x));
                v0.y *= g0.y / (1.f + fast_exp(-g0.y));
                v0.z *= g1.x / (1.f + fast_exp(-g1.x));
                v0.w *= g1.y / (1.f + fast_exp(-g1.y));
                v1.x *= g2.x / (1.f + fast_exp(-g2.x));
                v1.y *= g2.y / (1.f + fast_exp(-g2.y));
                v1.z *= g3.x / (1.f + fast_exp(-g3.x));
                v1.w *= g3.y / (1.f + fast_exp(-g3.y));
            }
            if (HOUT) {
                __half* C = (__half*)Cv;
                __half2 h[4];
                h[0] = __floats2half2_rn(v0.x, v0.y);
                h[1] = __floats2half2_rn(v0.z, v0.w);
                h[2] = __floats2half2_rn(v1.x, v1.y);
                h[3] = __floats2half2_rn(v1.z, v1.w);
                *(uint4*)&C[row_g * ldc + col_g] = *(uint4*)h;
            } else {
                float* C = (float*)Cv;
                *(float4*)&C[row_g * ldc + col_g] = v0;
                *(float4*)&C[row_g * ldc + col_g + 4] = v1;
            }
            __syncwarp();
        }
    }
#undef CAS_LOAD
}

// ============================================================
// PV cp.async (R10-proven)
// ============================================================
#define PV_APITCH 72
#define PV_ASTAGE (128 * PV_APITCH)
#define PV_BPITCH 136
#define PV_BSTAGE (64 * PV_BPITCH)
#define PV_SLOT   (PV_ASTAGE + PV_BSTAGE)
#define PV_SMEM_BYTES (3 * PV_SLOT * 2)

__global__ void __launch_bounds__(256, 2)
hpv_cas(const __half* __restrict__ p, const __half* __restrict__ v, int ldv,
        __half* __restrict__ out)
{
    extern __shared__ __half csmem[];
    const uint32_t sm32 = (uint32_t)__cvta_generic_to_shared(csmem);

    const int z = blockIdx.z;
    const int b = z / NH, h = z % NH, kvh = h / GRP;
    const int m0 = blockIdx.y * 128;
    const __half* A = p + (size_t)z * SEQ * SEQ;
    const __half* B = v + (size_t)b * SEQ * ldv + (size_t)kvh * HD;
    __half* C = out + (size_t)b * SEQ * HIDN + (size_t)h * HD;

    const int tid  = threadIdx.x;
    const int wid  = tid >> 5;
    const int lane = tid & 31;
    const int wm = wid & 1, wn = wid >> 1;

    CFragH c[4][2];
#pragma unroll
    for (int i = 0; i < 4; i++)
#pragma unroll
        for (int j = 0; j < 2; j++) wmma::fill_fragment(c[i][j], 0.f);

    const int arow = tid >> 1;
    const int acb  = (tid & 1) << 5;
    const int brow = tid >> 2;
    const int bcb  = (tid & 3) << 5;
    const __half* gA = A + (size_t)(m0 + arow) * SEQ + acb;
    const uint32_t tA = sm32 + (uint32_t)(arow * PV_APITCH + acb) * 2u;
    const uint32_t tB = sm32 + (uint32_t)(PV_ASTAGE + brow * PV_BPITCH + bcb) * 2u;

#define PV_LOAD(slot, k0) do {                                          \
        const uint32_t _o = (uint32_t)(slot) * (PV_SLOT * 2u);          \
        const __half* _gb = B + (size_t)((k0) + brow) * ldv + bcb;      \
        _Pragma("unroll")                                               \
        for (int _u = 0; _u < 4; _u++) {                                \
            cp16(tA + _o + _u * 16u, gA + (k0) + _u * 8);               \
            cp16(tB + _o + _u * 16u, _gb + _u * 8);                     \
        }                                                               \
    } while (0)

    const int nt = (m0 + 128) / BKC;

    PV_LOAD(0, 0);    cp_commit();
    PV_LOAD(1, BKC);  cp_commit();

    for (int t = 0; t < nt; t++) {
        cp_wait<1>();
        __syncthreads();
        if (t + 2 < nt) PV_LOAD((t + 2) % 3, (t + 2) * BKC);
        cp_commit();

        const __half* sA = csmem + (t % 3) * PV_SLOT;
        const __half* sB = sA + PV_ASTAGE;
#pragma unroll
        for (int ks = 0; ks < BKC; ks += 16) {
            AFragH af[4];
            BFragHR bf[2];
#pragma unroll
            for (int i = 0; i < 4; i++)
                wmma::load_matrix_sync(af[i], sA + (wm * 64 + i * 16) * PV_APITCH + ks, PV_APITCH);
#pragma unroll
            for (int j = 0; j < 2; j++)
                wmma::load_matrix_sync(bf[j], sB + ks * PV_BPITCH + (wn * 32 + j * 16), PV_BPITCH);
#pragma unroll
            for (int i = 0; i < 4; i++)
#pragma unroll
                for (int j = 0; j < 2; j++)
                    wmma::mma_sync(c[i][j], af[i], bf[j], c[i][j]);
        }
    }
    __syncthreads();

    float* stage = reinterpret_cast<float*>(csmem) + wid * 256;
    const int r  = lane >> 1;
    const int cq = (lane & 1) << 3;
#pragma unroll
    for (int i = 0; i < 4; i++) {
#pragma unroll
        for (int j = 0; j < 2; j++) {
            wmma::store_matrix_sync(stage, c[i][j], 16, wmma::mem_row_major);
            __syncwarp();
            const size_t row_g = (size_t)(m0 + wm * 64 + i * 16 + r);
            const size_t col_g = (size_t)(wn * 32 + j * 16 + cq);
            float4 v0 = *(float4*)&stage[r * 16 + cq];
            float4 v1 = *(float4*)&stage[r * 16 + cq + 4];
            __half2 hh[4];
            hh[0] = __floats2half2_rn(v0.x, v0.y);
            hh[1] = __floats2half2_rn(v0.z, v0.w);
            hh[2] = __floats2half2_rn(v1.x, v1.y);
            hh[3] = __floats2half2_rn(v1.z, v1.w);
            *(uint4*)&C[row_g * HIDN + col_g] = *(uint4*)hh;
            __syncwarp();
        }
    }
#undef PV_LOAD
}

// ============================================================
// Scores (R10-proven): q16(prescaled).k16 + analytic mask
// ============================================================
#define BM 128
#define BN 128
#define BK 32
#define HPITCH 40
#define HSTAGE (128 * HPITCH)

__global__ void __launch_bounds__(256, 2)
hscores(const __half* __restrict__ q, const __half* __restrict__ k,
        float* __restrict__ scores)
{
    if (blockIdx.x > blockIdx.y) return;

    const int z = blockIdx.z;
    const int b = z / NH, h = z % NH, kvh = h / GRP;
    const int m0 = blockIdx.y * BM;
    const int n0 = blockIdx.x * BN;
    const __half* A = q + (size_t)b * SEQ * HIDN + (size_t)h * HD;
    const __half* B = k + (size_t)b * SEQ * KVW + (size_t)kvh * HD;
    float* C = scores + (size_t)z * SEQ * SEQ;
    const bool diag = (blockIdx.x == blockIdx.y);

    __shared__ __align__(16) __half smem[4 * HSTAGE];
    __half* sA[2] = { smem,              smem + HSTAGE };
    __half* sB[2] = { smem + 2 * HSTAGE, smem + 3 * HSTAGE };

    const int tid  = threadIdx.x;
    const int wid  = tid >> 5;
    const int lane = tid & 31;
    const int wm = wid & 1, wn = wid >> 1;

    CFragH c[4][2];
#pragma unroll
    for (int i = 0; i < 4; i++)
#pragma unroll
        for (int jj = 0; jj < 2; jj++) wmma::fill_fragment(c[i][jj], 0.f);

    const int row = tid >> 1;
    const int c0  = (tid & 1) << 4;
    const __half* gA = A + (size_t)(m0 + row) * HIDN + c0;
    const __half* gB = B + (size_t)(n0 + row) * KVW + c0;

    uint4 ra0, ra1, rb0, rb1;
    ra0 = *(const uint4*)(gA);
    ra1 = *(const uint4*)(gA + 8);
    rb0 = *(const uint4*)(gB);
    rb1 = *(const uint4*)(gB + 8);
    {
        __half* a = sA[0] + row * HPITCH + c0;
        *(uint4*)a = ra0; *(uint4*)(a + 8) = ra1;
        __half* bb = sB[0] + row * HPITCH + c0;
        *(uint4*)bb = rb0; *(uint4*)(bb + 8) = rb1;
    }
    __syncthreads();

    const int nt = HD / BK;
    for (int t = 0; t < nt; t++) {
        const int cur = t & 1;
        if (t + 1 < nt) {
            const int k0 = (t + 1) * BK;
            ra0 = *(const uint4*)(gA + k0);
            ra1 = *(const uint4*)(gA + k0 + 8);
            rb0 = *(const uint4*)(gB + k0);
            rb1 = *(const uint4*)(gB + k0 + 8);
        }
#pragma unroll
        for (int ks = 0; ks < BK; ks += 16) {
            AFragH af[4];
            BFragHC bf[2];
#pragma unroll
            for (int i = 0; i < 4; i++)
                wmma::load_matrix_sync(af[i], sA[cur] + (wm * 64 + i * 16) * HPITCH + ks, HPITCH);
#pragma unroll
            for (int jj = 0; jj < 2; jj++)
                wmma::load_matrix_sync(bf[jj], sB[cur] + (wn * 32 + jj * 16) * HPITCH + ks, HPITCH);
#pragma unroll
            for (int i = 0; i < 4; i++)
#pragma unroll
                for (int jj = 0; jj < 2; jj++)
                    wmma::mma_sync(c[i][jj], af[i], bf[jj], c[i][jj]);
        }
        if (t + 1 < nt) {
            const int nxt = cur ^ 1;
            __half* a = sA[nxt] + row * HPITCH + c0;
            *(uint4*)a = ra0; *(uint4*)(a + 8) = ra1;
            __half* bb = sB[nxt] + row * HPITCH + c0;
            *(uint4*)bb = rb0; *(uint4*)(bb + 8) = rb1;
        }
        __syncthreads();
    }

    float* stage = reinterpret_cast<float*>(smem) + wid * 256;
    const int r  = lane >> 1;
    const int cq = (lane & 1) << 3;
#pragma unroll
    for (int i = 0; i < 4; i++) {
#pragma unroll
        for (int jj = 0; jj < 2; jj++) {
            wmma::store_matrix_sync(stage, c[i][jj], 16, wmma::mem_row_major);
            __syncwarp();
            const size_t row_g = (size_t)(m0 + wm * 64 + i * 16 + r);
            const size_t col_g = (size_t)(n0 + wn * 32 + jj * 16 + cq);
            float4 v0 = *(float4*)&stage[r * 16 + cq];
            float4 v1 = *(float4*)&stage[r * 16 + cq + 4];
            if (diag) {
                if (col_g + 0 > row_g) v0.x += NEGV;
                if (col_g + 1 > row_g) v0.y += NEGV;
                if (col_g + 2 > row_g) v0.z += NEGV;
                if (col_g + 3 > row_g) v0.w += NEGV;
                if (col_g + 4 > row_g) v1.x += NEGV;
                if (col_g + 5 > row_g) v1.y += NEGV;
                if (col_g + 6 > row_g) v1.z += NEGV;
                if (col_g + 7 > row_g) v1.w += NEGV;
            }
            *(float4*)&C[row_g * SEQ + col_g] = v0;
            *(float4*)&C[row_g * SEQ + col_g + 4] = v1;
            __syncwarp();
        }
    }
}

// ---------------- elementwise / reduction kernels ----------------

// fp32->fp16, 16 floats per thread per iter (MLP=4 independent float4 loads)
__global__ void __launch_bounds__(256)
f2h_kernel(const float* __restrict__ in, __half* __restrict__ out, int n)
{
    int i = (blockIdx.x * blockDim.x + threadIdx.x) * 16;
    int stride = gridDim.x * blockDim.x * 16;
    for (; i < n; i += stride) {
        float4 v0 = *(const float4*)(in + i);
        float4 v1 = *(const float4*)(in + i + 4);
        float4 v2 = *(const float4*)(in + i + 8);
        float4 v3 = *(const float4*)(in + i + 12);
        __half2* o = (__half2*)(out + i);
        o[0] = __floats2half2_rn(v0.x, v0.y);
        o[1] = __floats2half2_rn(v0.z, v0.w);
        o[2] = __floats2half2_rn(v1.x, v1.y);
        o[3] = __floats2half2_rn(v1.z, v1.w);
        o[4] = __floats2half2_rn(v2.x, v2.y);
        o[5] = __floats2half2_rn(v2.z, v2.w);
        o[6] = __floats2half2_rn(v3.x, v3.y);
        o[7] = __floats2half2_rn(v3.z, v3.w);
    }
}

__global__ void __launch_bounds__(256)
bias_concat_kernel(const float* __restrict__ bq, const float* __restrict__ bk,
                   const float* __restrict__ bv, float* __restrict__ dst)
{
    int i = blockIdx.x * blockDim.x + threadIdx.x;
    if (i < HIDN) dst[i] = bq[i];
    else if (i < HIDN + KVW) dst[i] = bk[i - HIDN];
    else if (i < NQKV) dst[i] = bv[i - HIDN - KVW];
}

// length-aware softmax with polynomial exp (no MUFU)
__global__ void __launch_bounds__(256)
softmax_kernel(const float* __restrict__ s, __half* __restrict__ p16)
{
    const size_t base = (size_t)blockIdx.x * SEQ;
    const int r = blockIdx.x & (SEQ - 1);
    const int L = ((r >> 7) + 1) << 7;
    const int tid = threadIdx.x;
    __shared__ float red[8];

    float vals[4];
    float mx = -1e30f;
    int cnt = 0;
    for (int idx = tid; idx < L; idx += 256) {
        vals[cnt] = s[base + idx];
        mx = fmaxf(mx, vals[cnt]);
        cnt++;
    }
#pragma unroll
    for (int o = 16; o > 0; o >>= 1) mx = fmaxf(mx, __shfl_xor_sync(0xffffffffu, mx, o));
    if ((tid & 31) == 0) red[tid >> 5] = mx;
    __syncthreads();
    float m2 = fmaxf(fmaxf(fmaxf(red[0], red[1]), fmaxf(red[2], red[3])),
                     fmaxf(fmaxf(red[4], red[5]), fmaxf(red[6], red[7])));
    __syncthreads();

    float sum = 0.f;
    for (int c = 0; c < cnt; c++) {
        vals[c] = fast_exp(vals[c] - m2);
        sum += vals[c];
    }
#pragma unroll
    for (int o = 16; o > 0; o >>= 1) sum += __shfl_xor_sync(0xffffffffu, sum, o);
    if ((tid & 31) == 0) red[tid >> 5] = sum;
    __syncthreads();
    float tot = red[0] + red[1] + red[2] + red[3] + red[4] + red[5] + red[6] + red[7];
    float inv = 1.f / tot;
    int c = 0;
    for (int idx = tid; idx < L; idx += 256, c++)
        p16[base + idx] = __float2half_rn(vals[c] * inv);
}

__global__ void __launch_bounds__(256)
rmsnorm_h_kernel(const float* __restrict__ x, const float* __restrict__ w,
                 __half* __restrict__ out)
{
    const size_t base = (size_t)blockIdx.x * HIDN;
    const int tid = threadIdx.x;
    __shared__ float red[8];

    float v[8];
    float ss = 0.f;
#pragma unroll
    for (int jj = 0; jj < 8; jj++) {
        v[jj] = x[base + tid + jj * 256];
        ss += v[jj] * v[jj];
    }
#pragma unroll
    for (int o = 16; o > 0; o >>= 1) ss += __shfl_xor_sync(0xffffffffu, ss, o);
    if ((tid & 31) == 0) red[tid >> 5] = ss;
    __syncthreads();
    float tot = red[0] + red[1] + red[2] + red[3] + red[4] + red[5] + red[6] + red[7];
    float r = rsqrtf(tot * (1.f / HIDN) + EPSV);
#pragma unroll
    for (int jj = 0; jj < 8; jj++)
        out[base + tid + jj * 256] = __float2half_rn(v[jj] * r * w[tid + jj * 256]);
}

__global__ void __launch_bounds__(128)
head_rms_rope_h_kernel(const __half* __restrict__ buf, int instride, int inoff,
                       const float* __restrict__ w,
                       const float* __restrict__ cs, const float* __restrict__ sn,
                       __half* __restrict__ out16, int outstride, float outscale)
{
    const int t = blockIdx.x;
    const int h = blockIdx.y;
    const int i = threadIdx.x;
    const size_t iidx = (size_t)t * instride + inoff + h * HD + i;
    const size_t oidx = (size_t)t * outstride + h * HD + i;

    float v = __half2float(buf[iidx]);
    float ss = v * v;
#pragma unroll
    for (int o = 16; o > 0; o >>= 1) ss += __shfl_xor_sync(0xffffffffu, ss, o);
    __shared__ float red[4];
    if ((i & 31) == 0) red[i >> 5] = ss;
    __syncthreads();
    float tot = red[0] + red[1] + red[2] + red[3];
    float n = v * rsqrtf(tot * (1.f / HD) + EPSV) * w[i];

    __shared__ float sm[HD];
    sm[i] = n;
    __syncthreads();
    float rot = (i < 64) ? -sm[i + 64] : sm[i - 64];
    float r = (n * cs[(size_t)t * HD + i] + rot * sn[(size_t)t * HD + i]) * outscale;
    out16[oidx] = __float2half_rn(r);
}

extern "C" void kernel_launch(void* const* d_in, const int* in_sizes, int n_in,
                              void* d_out, int out_size)
{
    const float* x    = (const float*)d_in[0];
    const float* cosv = (const float*)d_in[1];
    const float* sinv = (const float*)d_in[2];
    const float* wq   = (const float*)d_in[4];
    const float* bq   = (const float*)d_in[5];
    const float* wk   = (const float*)d_in[6];
    const float* bk   = (const float*)d_in[7];
    const float* wv   = (const float*)d_in[8];
    const float* bv   = (const float*)d_in[9];
    const float* wo   = (const float*)d_in[10];
    const float* qw   = (const float*)d_in[11];
    const float* kw   = (const float*)d_in[12];
    const float* ln1  = (const float*)d_in[13];
    const float* ln2  = (const float*)d_in[14];
    const float* wg   = (const float*)d_in[15];
    const float* wu   = (const float*)d_in[16];
    const float* wd   = (const float*)d_in[17];
    float* out = (float*)d_out;

    float* s = nullptr;
    cudaGetSymbolAddress((void**)&s, g_scratch);
    __half* hs = nullptr;
    cudaGetSymbolAddress((void**)&hs, g_hscratch);

    float* scores = s + OFF_SCORES;
    float* x2     = s + OFF_X2;
    float* biasc  = s + OFF_BIAS;

    __half* hwqkv  = hs + HW_QKV;
    __half* hwo    = hs + HW_O;
    __half* hwg    = hs + HW_G;
    __half* hwu    = hs + HW_U;
    __half* hwd    = hs + HW_D;
    __half* h16    = hs + H_H16;
    __half* qkv16  = hs + H_QKV16;
    __half* q16    = hs + H_Q16;
    __half* k16    = hs + H_K16;
    __half* p16    = hs + H_P16;
    __half* at16   = hs + H_ATTN16;
    __half* g16    = hs + H_G16;

    cudaFuncSetAttribute(casgemm_tn<1, 1>, cudaFuncAttributeMaxDynamicSharedMemorySize, CAS_SMEM_BYTES);
    cudaFuncSetAttribute(casgemm_tn<2, 0>, cudaFuncAttributeMaxDynamicSharedMemorySize, CAS_SMEM_BYTES);
    cudaFuncSetAttribute(casgemm_tn<0, 1>, cudaFuncAttributeMaxDynamicSharedMemorySize, CAS_SMEM_BYTES);
    cudaFuncSetAttribute(casgemm_tn<3, 1>, cudaFuncAttributeMaxDynamicSharedMemorySize, CAS_SMEM_BYTES);
    cudaFuncSetAttribute(hpv_cas,          cudaFuncAttributeMaxDynamicSharedMemorySize, PV_SMEM_BYTES);

    // 0. weights fp32 -> fp16 (QKV concatenated)
    f2h_kernel<<<1024, 256>>>(wq, hwqkv,                       HIDN * HIDN);
    f2h_kernel<<<256,  256>>>(wk, hwqkv + HIDN * HIDN,         KVW * HIDN);
    f2h_kernel<<<256,  256>>>(wv, hwqkv + (HIDN + KVW) * HIDN, KVW * HIDN);
    f2h_kernel<<<1024, 256>>>(wo, hwo, HIDN * HIDN);
    f2h_kernel<<<4096, 256>>>(wg, hwg, FF * HIDN);
    f2h_kernel<<<4096, 256>>>(wu, hwu, FF * HIDN);
    f2h_kernel<<<4096, 256>>>(wd, hwd, HIDN * FF);
    bias_concat_kernel<<<12, 256>>>(bq, bk, bv, biasc);

    // 1. h16 = rmsnorm(x, ln1)
    rmsnorm_h_kernel<<<T_TOK, 256>>>(x, ln1, h16);

    // 2. fused QKV projection (+bias) -> fp16 qkv16
    casgemm_tn<1, 1><<<dim3(NQKV / 128, T_TOK / 128), 256, CAS_SMEM_BYTES>>>(
        h16, HIDN, hwqkv, HIDN, qkv16, NQKV, HIDN, biasc, nullptr, nullptr);

    // 3-4. per-head RMS + RoPE -> q16 (pre-scaled) / k16 ; V stays in qkv16
    head_rms_rope_h_kernel<<<dim3(T_TOK, NH),  HD>>>(qkv16, NQKV, 0,    qw, cosv, sinv, q16, HIDN, SCALE);
    head_rms_rope_h_kernel<<<dim3(T_TOK, NKV), HD>>>(qkv16, NQKV, HIDN, kw, cosv, sinv, k16, KVW, 1.0f);

    // 5. scores (lower triangle, analytic mask)
    hscores<<<dim3(SEQ / BN, SEQ / BM, BATCH * NH), 256>>>(q16, k16, scores);

    // 6. softmax -> p16 (polynomial exp)
    softmax_kernel<<<BATCH * NH * SEQ, 256>>>(scores, p16);

    // 7. attn16 = P @ V (cp.async; V in-place in qkv16)
    hpv_cas<<<dim3(1, SEQ / 128, BATCH * NH), 256, PV_SMEM_BYTES>>>(
        p16, qkv16 + HIDN + KVW, NQKV, at16);

    // 8. x2 = x + attn @ wo^T
    casgemm_tn<2, 0><<<dim3(HIDN / 128, T_TOK / 128), 256, CAS_SMEM_BYTES>>>(
        at16, HIDN, hwo, HIDN, x2, HIDN, HIDN, nullptr, x, nullptr);

    // 9. h16 = rmsnorm(x2, ln2)
    rmsnorm_h_kernel<<<T_TOK, 256>>>(x2, ln2, h16);

    // 10. gate -> g16 (fp16)
    casgemm_tn<0, 1><<<dim3(FF / 128, T_TOK / 128), 256, CAS_SMEM_BYTES>>>(
        h16, HIDN, hwg, HIDN, g16, FF, HIDN, nullptr, nullptr, nullptr);

    // 11. up + fused silu: g16 = silu(g16) * up (in place, polynomial exp)
    casgemm_tn<3, 1><<<dim3(FF / 128, T_TOK / 128), 256, CAS_SMEM_BYTES>>>(
        h16, HIDN, hwu, HIDN, g16, FF, HIDN, nullptr, nullptr, g16);

    // 12. out = x2 + g16 @ wd^T
    casgemm_tn<2, 0><<<dim3(HIDN / 128, T_TOK / 128), 256, CAS_SMEM_BYTES>>>(
        g16, FF, hwd, FF, out, HIDN, FF, nullptr, x2, nullptr);
}

// round 13
// speedup vs baseline: 1.0734x; 1.0510x over previous
#include <cuda_runtime.h>
#include <cuda_fp16.h>
#include <mma.h>
#include <math.h>
#include <stdint.h>

using namespace nvcuda;

// ---------------- problem constants ----------------
#define T_TOK 4096
#define HIDN  2048
#define NH    16
#define NKV   4
#define HD    128
#define FF    8192
#define BATCH 4
#define SEQ   1024
#define GRP   (NH / NKV)
#define KVW   (NKV * HD)          // 512
#define NQKV  (HIDN + 2 * KVW)    // 3072
#define EPSV  1e-6f
#define SCALE 0.08838834764831845f
#define NEG16 -60000.0f           // fp16-safe mask value (underflows in softmax)

// ---------------- fp32 scratch ----------------
#define OFF_X2     ((size_t)0)           // 4096*2048
#define OFF_BIAS   ((size_t)8388608)     // 3072 (pad)
#define SCRATCH_FLOATS ((size_t)8392704)
__device__ float g_scratch[SCRATCH_FLOATS];

// ---------------- fp16 scratch ----------------
#define HW_QKV   ((size_t)0)
#define HW_O     ((size_t)6291456)
#define HW_G     ((size_t)10485760)
#define HW_U     ((size_t)27262976)
#define HW_D     ((size_t)44040192)
#define H_H16    ((size_t)60817408)
#define H_QKV16  ((size_t)69206016)
#define H_Q16    ((size_t)81788928)
#define H_K16    ((size_t)90177536)
#define H_P16    ((size_t)92274688)      // scores/probs, fp16, in place
#define H_ATTN16 ((size_t)159383552)
#define H_G16    ((size_t)167772160)
#define HSCRATCH_HALVES ((size_t)201326592)
__device__ __half g_hscratch[HSCRATCH_HALVES];

// ---------------- cp.async helpers ----------------
__device__ __forceinline__ void cp16(uint32_t dst, const void* src) {
    asm volatile("cp.async.cg.shared.global [%0], [%1], 16;" :: "r"(dst), "l"(src));
}
__device__ __forceinline__ void cp_commit() {
    asm volatile("cp.async.commit_group;");
}
template <int N>
__device__ __forceinline__ void cp_wait() {
    asm volatile("cp.async.wait_group %0;" :: "n"(N));
}

typedef wmma::fragment<wmma::matrix_a, 16, 16, 16, __half, wmma::row_major> AFragH;
typedef wmma::fragment<wmma::matrix_b, 16, 16, 16, __half, wmma::col_major> BFragHC;
typedef wmma::fragment<wmma::matrix_b, 16, 16, 16, __half, wmma::row_major> BFragHR;
typedef wmma::fragment<wmma::accumulator, 16, 16, 16, float> CFragH;

// ============================================================
// casgemm (R9/R10-proven): 128x128 tile, 256 thr, BK=64,
// 3 stages, 2 CTA/SM.  C[M,N] = A[M,K] @ B[N,K]^T.
// EPI: 0 none, 1 +bias, 2 +res(fp32), 3 silu(resH)*acc.
// HOUT: 0 fp32 C, 1 fp16 C.
// ============================================================
#define BKC 64
#define CPITCH 72
#define CSTAGE (128 * CPITCH)
#define CAS_SMEM_BYTES (3 * 2 * CSTAGE * 2)   // 110592 B

template <int EPI, int HOUT>
__global__ void __launch_bounds__(256, 2)
casgemm_tn(const __half* __restrict__ A, int lda,
           const __half* __restrict__ B, int ldb,
           void* __restrict__ Cv, int ldc, int K,
           const float* __restrict__ bias,
           const float* __restrict__ res,
           const __half* __restrict__ resH)
{
    extern __shared__ __half csmem[];
    const uint32_t sm32 = (uint32_t)__cvta_generic_to_shared(csmem);

    const int tid  = threadIdx.x;
    const int wid  = tid >> 5;
    const int lane = tid & 31;
    const int m0 = blockIdx.y * 128;
    const int n0 = blockIdx.x * 128;
    const int wm = wid & 1, wn = wid >> 1;

    CFragH c[4][2];
#pragma unroll
    for (int i = 0; i < 4; i++)
#pragma unroll
        for (int j = 0; j < 2; j++) wmma::fill_fragment(c[i][j], 0.f);

    const int row = tid >> 1;
    const int cb  = (tid & 1) << 5;
    const __half* gA = A + (size_t)(m0 + row) * lda + cb;
    const __half* gB = B + (size_t)(n0 + row) * ldb + cb;
    const uint32_t tA = sm32 + (uint32_t)(row * CPITCH + cb) * 2u;
    const uint32_t tB = tA + (uint32_t)CSTAGE * 2u;

#define CAS_LOAD(slot, k0) do {                                         \
        const uint32_t _o = (uint32_t)(slot) * (2u * CSTAGE * 2u);      \
        _Pragma("unroll")                                               \
        for (int _u = 0; _u < 4; _u++) {                                \
            cp16(tA + _o + _u * 16u, gA + (k0) + _u * 8);               \
            cp16(tB + _o + _u * 16u, gB + (k0) + _u * 8);               \
        }                                                               \
    } while (0)

    const int nt = K / BKC;

    CAS_LOAD(0, 0);      cp_commit();
    CAS_LOAD(1, BKC);    cp_commit();

    for (int t = 0; t < nt; t++) {
        cp_wait<1>();
        __syncthreads();
        if (t + 2 < nt) CAS_LOAD((t + 2) % 3, (t + 2) * BKC);
        cp_commit();

        const __half* sA = csmem + (t % 3) * 2 * CSTAGE;
        const __half* sB = sA + CSTAGE;
#pragma unroll
        for (int ks = 0; ks < BKC; ks += 16) {
            AFragH af[4];
            BFragHC bf[2];
#pragma unroll
            for (int i = 0; i < 4; i++)
                wmma::load_matrix_sync(af[i], sA + (wm * 64 + i * 16) * CPITCH + ks, CPITCH);
#pragma unroll
            for (int j = 0; j < 2; j++)
                wmma::load_matrix_sync(bf[j], sB + (wn * 32 + j * 16) * CPITCH + ks, CPITCH);
#pragma unroll
            for (int i = 0; i < 4; i++)
#pragma unroll
                for (int j = 0; j < 2; j++)
                    wmma::mma_sync(c[i][j], af[i], bf[j], c[i][j]);
        }
    }
    __syncthreads();

    float* stage = reinterpret_cast<float*>(csmem) + wid * 256;
    const int r  = lane >> 1;
    const int cq = (lane & 1) << 3;
#pragma unroll
    for (int i = 0; i < 4; i++) {
#pragma unroll
        for (int j = 0; j < 2; j++) {
            wmma::store_matrix_sync(stage, c[i][j], 16, wmma::mem_row_major);
            __syncwarp();
            const size_t row_g = (size_t)(m0 + wm * 64 + i * 16 + r);
            const size_t col_g = (size_t)(n0 + wn * 32 + j * 16 + cq);
            float4 v0 = *(float4*)&stage[r * 16 + cq];
            float4 v1 = *(float4*)&stage[r * 16 + cq + 4];
            if (EPI == 1) {
                float4 b0 = *(const float4*)&bias[col_g];
                float4 b1 = *(const float4*)&bias[col_g + 4];
                v0.x += b0.x; v0.y += b0.y; v0.z += b0.z; v0.w += b0.w;
                v1.x += b1.x; v1.y += b1.y; v1.z += b1.z; v1.w += b1.w;
            }
            if (EPI == 2) {
                float4 r0 = *(const float4*)&res[row_g * ldc + col_g];
                float4 r1 = *(const float4*)&res[row_g * ldc + col_g + 4];
                v0.x += r0.x; v0.y += r0.y; v0.z += r0.z; v0.w += r0.w;
                v1.x += r1.x; v1.y += r1.y; v1.z += r1.z; v1.w += r1.w;
            }
            if (EPI == 3) {
                uint4 gu = *(const uint4*)&resH[row_g * ldc + col_g];
                __half2* gh = (__half2*)&gu;
                float2 g0 = __half22float2(gh[0]);
                float2 g1 = __half22float2(gh[1]);
                float2 g2 = __half22float2(gh[2]);
                float2 g3 = __half22float2(gh[3]);
                v0.x *= g0.x / (1.f + expf(-g0.x));
                v0.y *= g0.y / (1.f + expf(-g0.y));
                v0.z *= g1.x / (1.f + expf(-g1.x));
                v0.w *= g1.y / (1.f + expf(-g1.y));
                v1.x *= g2.x / (1.f + expf(-g2.x));
                v1.y *= g2.y / (1.f + expf(-g2.y));
                v1.z *= g3.x / (1.f + expf(-g3.x));
                v1.w *= g3.y / (1.f + expf(-g3.y));
            }
            if (HOUT) {
                __half* C = (__half*)Cv;
                __half2 h[4];
                h[0] = __floats2half2_rn(v0.x, v0.y);
                h[1] = __floats2half2_rn(v0.z, v0.w);
                h[2] = __floats2half2_rn(v1.x, v1.y);
                h[3] = __floats2half2_rn(v1.z, v1.w);
                *(uint4*)&C[row_g * ldc + col_g] = *(uint4*)h;
            } else {
                float* C = (float*)Cv;
                *(float4*)&C[row_g * ldc + col_g] = v0;
                *(float4*)&C[row_g * ldc + col_g + 4] = v1;
            }
            __syncwarp();
        }
    }
#undef CAS_LOAD
}

// ============================================================
// PV cp.async (R10-proven)
// ============================================================
#define PV_APITCH 72
#define PV_ASTAGE (128 * PV_APITCH)
#define PV_BPITCH 136
#define PV_BSTAGE (64 * PV_BPITCH)
#define PV_SLOT   (PV_ASTAGE + PV_BSTAGE)
#define PV_SMEM_BYTES (3 * PV_SLOT * 2)

__global__ void __launch_bounds__(256, 2)
hpv_cas(const __half* __restrict__ p, const __half* __restrict__ v, int ldv,
        __half* __restrict__ out)
{
    extern __shared__ __half csmem[];
    const uint32_t sm32 = (uint32_t)__cvta_generic_to_shared(csmem);

    const int z = blockIdx.z;
    const int b = z / NH, h = z % NH, kvh = h / GRP;
    const int m0 = blockIdx.y * 128;
    const __half* A = p + (size_t)z * SEQ * SEQ;
    const __half* B = v + (size_t)b * SEQ * ldv + (size_t)kvh * HD;
    __half* C = out + (size_t)b * SEQ * HIDN + (size_t)h * HD;

    const int tid  = threadIdx.x;
    const int wid  = tid >> 5;
    const int lane = tid & 31;
    const int wm = wid & 1, wn = wid >> 1;

    CFragH c[4][2];
#pragma unroll
    for (int i = 0; i < 4; i++)
#pragma unroll
        for (int j = 0; j < 2; j++) wmma::fill_fragment(c[i][j], 0.f);

    const int arow = tid >> 1;
    const int acb  = (tid & 1) << 5;
    const int brow = tid >> 2;
    const int bcb  = (tid & 3) << 5;
    const __half* gA = A + (size_t)(m0 + arow) * SEQ + acb;
    const uint32_t tA = sm32 + (uint32_t)(arow * PV_APITCH + acb) * 2u;
    const uint32_t tB = sm32 + (uint32_t)(PV_ASTAGE + brow * PV_BPITCH + bcb) * 2u;

#define PV_LOAD(slot, k0) do {                                          \
        const uint32_t _o = (uint32_t)(slot) * (PV_SLOT * 2u);          \
        const __half* _gb = B + (size_t)((k0) + brow) * ldv + bcb;      \
        _Pragma("unroll")                                               \
        for (int _u = 0; _u < 4; _u++) {                                \
            cp16(tA + _o + _u * 16u, gA + (k0) + _u * 8);               \
            cp16(tB + _o + _u * 16u, _gb + _u * 8);                     \
        }                                                               \
    } while (0)

    const int nt = (m0 + 128) / BKC;

    PV_LOAD(0, 0);    cp_commit();
    PV_LOAD(1, BKC);  cp_commit();

    for (int t = 0; t < nt; t++) {
        cp_wait<1>();
        __syncthreads();
        if (t + 2 < nt) PV_LOAD((t + 2) % 3, (t + 2) * BKC);
        cp_commit();

        const __half* sA = csmem + (t % 3) * PV_SLOT;
        const __half* sB = sA + PV_ASTAGE;
#pragma unroll
        for (int ks = 0; ks < BKC; ks += 16) {
            AFragH af[4];
            BFragHR bf[2];
#pragma unroll
            for (int i = 0; i < 4; i++)
                wmma::load_matrix_sync(af[i], sA + (wm * 64 + i * 16) * PV_APITCH + ks, PV_APITCH);
#pragma unroll
            for (int j = 0; j < 2; j++)
                wmma::load_matrix_sync(bf[j], sB + ks * PV_BPITCH + (wn * 32 + j * 16), PV_BPITCH);
#pragma unroll
            for (int i = 0; i < 4; i++)
#pragma unroll
                for (int j = 0; j < 2; j++)
                    wmma::mma_sync(c[i][j], af[i], bf[j], c[i][j]);
        }
    }
    __syncthreads();

    float* stage = reinterpret_cast<float*>(csmem) + wid * 256;
    const int r  = lane >> 1;
    const int cq = (lane & 1) << 3;
#pragma unroll
    for (int i = 0; i < 4; i++) {
#pragma unroll
        for (int j = 0; j < 2; j++) {
            wmma::store_matrix_sync(stage, c[i][j], 16, wmma::mem_row_major);
            __syncwarp();
            const size_t row_g = (size_t)(m0 + wm * 64 + i * 16 + r);
            const size_t col_g = (size_t)(wn * 32 + j * 16 + cq);
            float4 v0 = *(float4*)&stage[r * 16 + cq];
            float4 v1 = *(float4*)&stage[r * 16 + cq + 4];
            __half2 hh[4];
            hh[0] = __floats2half2_rn(v0.x, v0.y);
            hh[1] = __floats2half2_rn(v0.z, v0.w);
            hh[2] = __floats2half2_rn(v1.x, v1.y);
            hh[3] = __floats2half2_rn(v1.z, v1.w);
            *(uint4*)&C[row_g * HIDN + col_g] = *(uint4*)hh;
            __syncwarp();
        }
    }
#undef PV_LOAD
}

// ============================================================
// Scores -> fp16 (into p16 buffer): q16(prescaled).k16 + mask
// ============================================================
#define BM 128
#define BN 128
#define BK 32
#define HPITCH 40
#define HSTAGE (128 * HPITCH)

__global__ void __launch_bounds__(256, 2)
hscores(const __half* __restrict__ q, const __half* __restrict__ k,
        __half* __restrict__ scores)
{
    if (blockIdx.x > blockIdx.y) return;

    const int z = blockIdx.z;
    const int b = z / NH, h = z % NH, kvh = h / GRP;
    const int m0 = blockIdx.y * BM;
    const int n0 = blockIdx.x * BN;
    const __half* A = q + (size_t)b * SEQ * HIDN + (size_t)h * HD;
    const __half* B = k + (size_t)b * SEQ * KVW + (size_t)kvh * HD;
    __half* C = scores + (size_t)z * SEQ * SEQ;
    const bool diag = (blockIdx.x == blockIdx.y);

    __shared__ __align__(16) __half smem[4 * HSTAGE];
    __half* sA[2] = { smem,              smem + HSTAGE };
    __half* sB[2] = { smem + 2 * HSTAGE, smem + 3 * HSTAGE };

    const int tid  = threadIdx.x;
    const int wid  = tid >> 5;
    const int lane = tid & 31;
    const int wm = wid & 1, wn = wid >> 1;

    CFragH c[4][2];
#pragma unroll
    for (int i = 0; i < 4; i++)
#pragma unroll
        for (int jj = 0; jj < 2; jj++) wmma::fill_fragment(c[i][jj], 0.f);

    const int row = tid >> 1;
    const int c0  = (tid & 1) << 4;
    const __half* gA = A + (size_t)(m0 + row) * HIDN + c0;
    const __half* gB = B + (size_t)(n0 + row) * KVW + c0;

    uint4 ra0, ra1, rb0, rb1;
    ra0 = *(const uint4*)(gA);
    ra1 = *(const uint4*)(gA + 8);
    rb0 = *(const uint4*)(gB);
    rb1 = *(const uint4*)(gB + 8);
    {
        __half* a = sA[0] + row * HPITCH + c0;
        *(uint4*)a = ra0; *(uint4*)(a + 8) = ra1;
        __half* bb = sB[0] + row * HPITCH + c0;
        *(uint4*)bb = rb0; *(uint4*)(bb + 8) = rb1;
    }
    __syncthreads();

    const int nt = HD / BK;
    for (int t = 0; t < nt; t++) {
        const int cur = t & 1;
        if (t + 1 < nt) {
            const int k0 = (t + 1) * BK;
            ra0 = *(const uint4*)(gA + k0);
            ra1 = *(const uint4*)(gA + k0 + 8);
            rb0 = *(const uint4*)(gB + k0);
            rb1 = *(const uint4*)(gB + k0 + 8);
        }
#pragma unroll
        for (int ks = 0; ks < BK; ks += 16) {
            AFragH af[4];
            BFragHC bf[2];
#pragma unroll
            for (int i = 0; i < 4; i++)
                wmma::load_matrix_sync(af[i], sA[cur] + (wm * 64 + i * 16) * HPITCH + ks, HPITCH);
#pragma unroll
            for (int jj = 0; jj < 2; jj++)
                wmma::load_matrix_sync(bf[jj], sB[cur] + (wn * 32 + jj * 16) * HPITCH + ks, HPITCH);
#pragma unroll
            for (int i = 0; i < 4; i++)
#pragma unroll
                for (int jj = 0; jj < 2; jj++)
                    wmma::mma_sync(c[i][jj], af[i], bf[jj], c[i][jj]);
        }
        if (t + 1 < nt) {
            const int nxt = cur ^ 1;
            __half* a = sA[nxt] + row * HPITCH + c0;
            *(uint4*)a = ra0; *(uint4*)(a + 8) = ra1;
            __half* bb = sB[nxt] + row * HPITCH + c0;
            *(uint4*)bb = rb0; *(uint4*)(bb + 8) = rb1;
        }
        __syncthreads();
    }

    float* stage = reinterpret_cast<float*>(smem) + wid * 256;
    const int r  = lane >> 1;
    const int cq = (lane & 1) << 3;
#pragma unroll
    for (int i = 0; i < 4; i++) {
#pragma unroll
        for (int jj = 0; jj < 2; jj++) {
            wmma::store_matrix_sync(stage, c[i][jj], 16, wmma::mem_row_major);
            __syncwarp();
            const size_t row_g = (size_t)(m0 + wm * 64 + i * 16 + r);
            const size_t col_g = (size_t)(n0 + wn * 32 + jj * 16 + cq);
            float4 v0 = *(float4*)&stage[r * 16 + cq];
            float4 v1 = *(float4*)&stage[r * 16 + cq + 4];
            if (diag) {
                if (col_g + 0 > row_g) v0.x = NEG16;
                if (col_g + 1 > row_g) v0.y = NEG16;
                if (col_g + 2 > row_g) v0.z = NEG16;
                if (col_g + 3 > row_g) v0.w = NEG16;
                if (col_g + 4 > row_g) v1.x = NEG16;
                if (col_g + 5 > row_g) v1.y = NEG16;
                if (col_g + 6 > row_g) v1.z = NEG16;
                if (col_g + 7 > row_g) v1.w = NEG16;
            }
            __half2 hh[4];
            hh[0] = __floats2half2_rn(v0.x, v0.y);
            hh[1] = __floats2half2_rn(v0.z, v0.w);
            hh[2] = __floats2half2_rn(v1.x, v1.y);
            hh[3] = __floats2half2_rn(v1.z, v1.w);
            *(uint4*)&C[row_g * SEQ + col_g] = *(uint4*)hh;
            __syncwarp();
        }
    }
}

// ---------------- elementwise / reduction kernels ----------------

__global__ void __launch_bounds__(256)
f2h_kernel(const float* __restrict__ in, __half* __restrict__ out, int n)
{
    int i = (blockIdx.x * blockDim.x + threadIdx.x) * 4;
    int stride = gridDim.x * blockDim.x * 4;
    for (; i < n; i += stride) {
        float4 v = *(const float4*)(in + i);
        ((__half2*)(out + i))[0] = __floats2half2_rn(v.x, v.y);
        ((__half2*)(out + i))[1] = __floats2half2_rn(v.z, v.w);
    }
}

__global__ void __launch_bounds__(256)
bias_concat_kernel(const float* __restrict__ bq, const float* __restrict__ bk,
                   const float* __restrict__ bv, float* __restrict__ dst)
{
    int i = blockIdx.x * blockDim.x + threadIdx.x;
    if (i < HIDN) dst[i] = bq[i];
    else if (i < HIDN + KVW) dst[i] = bk[i - HIDN];
    else if (i < NQKV) dst[i] = bv[i - HIDN - KVW];
}

// length-aware softmax, fp16 in place
__global__ void __launch_bounds__(256)
softmax_kernel(__half* __restrict__ s)
{
    const size_t base = (size_t)blockIdx.x * SEQ;
    const int r = blockIdx.x & (SEQ - 1);
    const int L = ((r >> 7) + 1) << 7;
    const int tid = threadIdx.x;
    __shared__ float red[8];

    float vals[4];
    float mx = -1e30f;
    int cnt = 0;
    for (int idx = tid; idx < L; idx += 256) {
        vals[cnt] = __half2float(s[base + idx]);
        mx = fmaxf(mx, vals[cnt]);
        cnt++;
    }
#pragma unroll
    for (int o = 16; o > 0; o >>= 1) mx = fmaxf(mx, __shfl_xor_sync(0xffffffffu, mx, o));
    if ((tid & 31) == 0) red[tid >> 5] = mx;
    __syncthreads();
    float m2 = fmaxf(fmaxf(fmaxf(red[0], red[1]), fmaxf(red[2], red[3])),
                     fmaxf(fmaxf(red[4], red[5]), fmaxf(red[6], red[7])));
    __syncthreads();

    float sum = 0.f;
    for (int c = 0; c < cnt; c++) {
        vals[c] = expf(vals[c] - m2);
        sum += vals[c];
    }
#pragma unroll
    for (int o = 16; o > 0; o >>= 1) sum += __shfl_xor_sync(0xffffffffu, sum, o);
    if ((tid & 31) == 0) red[tid >> 5] = sum;
    __syncthreads();
    float tot = red[0] + red[1] + red[2] + red[3] + red[4] + red[5] + red[6] + red[7];
    float inv = 1.f / tot;
    int c = 0;
    for (int idx = tid; idx < L; idx += 256, c++)
        s[base + idx] = __float2half_rn(vals[c] * inv);
}

__global__ void __launch_bounds__(256)
rmsnorm_h_kernel(const float* __restrict__ x, const float* __restrict__ w,
                 __half* __restrict__ out)
{
    const size_t base = (size_t)blockIdx.x * HIDN;
    const int tid = threadIdx.x;
    __shared__ float red[8];

    float v[8];
    float ss = 0.f;
#pragma unroll
    for (int jj = 0; jj < 8; jj++) {
        v[jj] = x[base + tid + jj * 256];
        ss += v[jj] * v[jj];
    }
#pragma unroll
    for (int o = 16; o > 0; o >>= 1) ss += __shfl_xor_sync(0xffffffffu, ss, o);
    if ((tid & 31) == 0) red[tid >> 5] = ss;
    __syncthreads();
    float tot = red[0] + red[1] + red[2] + red[3] + red[4] + red[5] + red[6] + red[7];
    float r = rsqrtf(tot * (1.f / HIDN) + EPSV);
#pragma unroll
    for (int jj = 0; jj < 8; jj++)
        out[base + tid + jj * 256] = __float2half_rn(v[jj] * r * w[tid + jj * 256]);
}

__global__ void __launch_bounds__(128)
head_rms_rope_h_kernel(const __half* __restrict__ buf, int instride, int inoff,
                       const float* __restrict__ w,
                       const float* __restrict__ cs, const float* __restrict__ sn,
                       __half* __restrict__ out16, int outstride, float outscale)
{
    const int t = blockIdx.x;
    const int h = blockIdx.y;
    const int i = threadIdx.x;
    const size_t iidx = (size_t)t * instride + inoff + h * HD + i;
    const size_t oidx = (size_t)t * outstride + h * HD + i;

    float v = __half2float(buf[iidx]);
    float ss = v * v;
#pragma unroll
    for (int o = 16; o > 0; o >>= 1) ss += __shfl_xor_sync(0xffffffffu, ss, o);
    __shared__ float red[4];
    if ((i & 31) == 0) red[i >> 5] = ss;
    __syncthreads();
    float tot = red[0] + red[1] + red[2] + red[3];
    float n = v * rsqrtf(tot * (1.f / HD) + EPSV) * w[i];

    __shared__ float sm[HD];
    sm[i] = n;
    __syncthreads();
    float rot = (i < 64) ? -sm[i + 64] : sm[i - 64];
    float r = (n * cs[(size_t)t * HD + i] + rot * sn[(size_t)t * HD + i]) * outscale;
    out16[oidx] = __float2half_rn(r);
}

extern "C" void kernel_launch(void* const* d_in, const int* in_sizes, int n_in,
                              void* d_out, int out_size)
{
    const float* x    = (const float*)d_in[0];
    const float* cosv = (const float*)d_in[1];
    const float* sinv = (const float*)d_in[2];
    const float* wq   = (const float*)d_in[4];
    const float* bq   = (const float*)d_in[5];
    const float* wk   = (const float*)d_in[6];
    const float* bk   = (const float*)d_in[7];
    const float* wv   = (const float*)d_in[8];
    const float* bv   = (const float*)d_in[9];
    const float* wo   = (const float*)d_in[10];
    const float* qw   = (const float*)d_in[11];
    const float* kw   = (const float*)d_in[12];
    const float* ln1  = (const float*)d_in[13];
    const float* ln2  = (const float*)d_in[14];
    const float* wg   = (const float*)d_in[15];
    const float* wu   = (const float*)d_in[16];
    const float* wd   = (const float*)d_in[17];
    float* out = (float*)d_out;

    float* s = nullptr;
    cudaGetSymbolAddress((void**)&s, g_scratch);
    __half* hs = nullptr;
    cudaGetSymbolAddress((void**)&hs, g_hscratch);

    float* x2     = s + OFF_X2;
    float* biasc  = s + OFF_BIAS;

    __half* hwqkv  = hs + HW_QKV;
    __half* hwo    = hs + HW_O;
    __half* hwg    = hs + HW_G;
    __half* hwu    = hs + HW_U;
    __half* hwd    = hs + HW_D;
    __half* h16    = hs + H_H16;
    __half* qkv16  = hs + H_QKV16;
    __half* q16    = hs + H_Q16;
    __half* k16    = hs + H_K16;
    __half* p16    = hs + H_P16;
    __half* at16   = hs + H_ATTN16;
    __half* g16    = hs + H_G16;

    cudaFuncSetAttribute(casgemm_tn<1, 1>, cudaFuncAttributeMaxDynamicSharedMemorySize, CAS_SMEM_BYTES);
    cudaFuncSetAttribute(casgemm_tn<2, 0>, cudaFuncAttributeMaxDynamicSharedMemorySize, CAS_SMEM_BYTES);
    cudaFuncSetAttribute(casgemm_tn<0, 1>, cudaFuncAttributeMaxDynamicSharedMemorySize, CAS_SMEM_BYTES);
    cudaFuncSetAttribute(casgemm_tn<3, 1>, cudaFuncAttributeMaxDynamicSharedMemorySize, CAS_SMEM_BYTES);
    cudaFuncSetAttribute(hpv_cas,          cudaFuncAttributeMaxDynamicSharedMemorySize, PV_SMEM_BYTES);

    // 0. weights fp32 -> fp16 (QKV concatenated) — R10-proven config
    f2h_kernel<<<2048, 256>>>(wq, hwqkv,                       HIDN * HIDN);
    f2h_kernel<<<1024, 256>>>(wk, hwqkv + HIDN * HIDN,         KVW * HIDN);
    f2h_kernel<<<1024, 256>>>(wv, hwqkv + (HIDN + KVW) * HIDN, KVW * HIDN);
    f2h_kernel<<<2048, 256>>>(wo, hwo, HIDN * HIDN);
    f2h_kernel<<<4096, 256>>>(wg, hwg, FF * HIDN);
    f2h_kernel<<<4096, 256>>>(wu, hwu, FF * HIDN);
    f2h_kernel<<<4096, 256>>>(wd, hwd, HIDN * FF);
    bias_concat_kernel<<<12, 256>>>(bq, bk, bv, biasc);

    // 1. h16 = rmsnorm(x, ln1)
    rmsnorm_h_kernel<<<T_TOK, 256>>>(x, ln1, h16);

    // 2. fused QKV projection (+bias) -> fp16 qkv16
    casgemm_tn<1, 1><<<dim3(NQKV / 128, T_TOK / 128), 256, CAS_SMEM_BYTES>>>(
        h16, HIDN, hwqkv, HIDN, qkv16, NQKV, HIDN, biasc, nullptr, nullptr);

    // 3-4. per-head RMS + RoPE -> q16 (pre-scaled) / k16 ; V stays in qkv16
    head_rms_rope_h_kernel<<<dim3(T_TOK, NH),  HD>>>(qkv16, NQKV, 0,    qw, cosv, sinv, q16, HIDN, SCALE);
    head_rms_rope_h_kernel<<<dim3(T_TOK, NKV), HD>>>(qkv16, NQKV, HIDN, kw, cosv, sinv, k16, KVW, 1.0f);

    // 5. scores -> fp16 p16 buffer (lower triangle, analytic mask)
    hscores<<<dim3(SEQ / BN, SEQ / BM, BATCH * NH), 256>>>(q16, k16, p16);

    // 6. softmax in place on p16
    softmax_kernel<<<BATCH * NH * SEQ, 256>>>(p16);

    // 7. attn16 = P @ V (cp.async; V in-place in qkv16)
    hpv_cas<<<dim3(1, SEQ / 128, BATCH * NH), 256, PV_SMEM_BYTES>>>(
        p16, qkv16 + HIDN + KVW, NQKV, at16);

    // 8. x2 = x + attn @ wo^T
    casgemm_tn<2, 0><<<dim3(HIDN / 128, T_TOK / 128), 256, CAS_SMEM_BYTES>>>(
        at16, HIDN, hwo, HIDN, x2, HIDN, HIDN, nullptr, x, nullptr);

    // 9. h16 = rmsnorm(x2, ln2)
    rmsnorm_h_kernel<<<T_TOK, 256>>>(x2, ln2, h16);

    // 10. gate -> g16 (fp16)
    casgemm_tn<0, 1><<<dim3(FF / 128, T_TOK / 128), 256, CAS_SMEM_BYTES>>>(
        h16, HIDN, hwg, HIDN, g16, FF, HIDN, nullptr, nullptr, nullptr);

    // 11. up + fused silu: g16 = silu(g16) * up (in place)
    casgemm_tn<3, 1><<<dim3(FF / 128, T_TOK / 128), 256, CAS_SMEM_BYTES>>>(
        h16, HIDN, hwu, HIDN, g16, FF, HIDN, nullptr, nullptr, g16);

    // 12. out = x2 + g16 @ wd^T
    casgemm_tn<2, 0><<<dim3(HIDN / 128, T_TOK / 128), 256, CAS_SMEM_BYTES>>>(
        g16, FF, hwd, FF, out, HIDN, FF, nullptr, x2, nullptr);
}

// round 14
// speedup vs baseline: 1.0931x; 1.0183x over previous
#include <cuda_runtime.h>
#include <cuda_fp16.h>
#include <mma.h>
#include <math.h>
#include <stdint.h>

using namespace nvcuda;

// ---------------- problem constants ----------------
#define T_TOK 4096
#define HIDN  2048
#define NH    16
#define NKV   4
#define HD    128
#define FF    8192
#define BATCH 4
#define SEQ   1024
#define GRP   (NH / NKV)
#define KVW   (NKV * HD)          // 512
#define NQKV  (HIDN + 2 * KVW)    // 3072
#define EPSV  1e-6f
#define SCALE 0.08838834764831845f
#define NEG16 -60000.0f

// ---------------- fp32 scratch ----------------
#define OFF_X2     ((size_t)0)
#define OFF_BIAS   ((size_t)8388608)
#define SCRATCH_FLOATS ((size_t)8392704)
__device__ float g_scratch[SCRATCH_FLOATS];

// ---------------- fp16 scratch ----------------
#define HW_QKV   ((size_t)0)
#define HW_O     ((size_t)6291456)
#define HW_G     ((size_t)10485760)
#define HW_U     ((size_t)27262976)
#define HW_D     ((size_t)44040192)
#define H_H16    ((size_t)60817408)
#define H_QKV16  ((size_t)69206016)
#define H_Q16    ((size_t)81788928)
#define H_K16    ((size_t)90177536)
#define H_P16    ((size_t)92274688)
#define H_ATTN16 ((size_t)159383552)
#define H_G16    ((size_t)167772160)
#define HSCRATCH_HALVES ((size_t)201326592)
__device__ __half g_hscratch[HSCRATCH_HALVES];

// ---------------- cp.async helpers ----------------
__device__ __forceinline__ void cp16(uint32_t dst, const void* src) {
    asm volatile("cp.async.cg.shared.global [%0], [%1], 16;" :: "r"(dst), "l"(src));
}
__device__ __forceinline__ void cp_commit() {
    asm volatile("cp.async.commit_group;");
}
template <int N>
__device__ __forceinline__ void cp_wait() {
    asm volatile("cp.async.wait_group %0;" :: "n"(N));
}

typedef wmma::fragment<wmma::matrix_a, 16, 16, 16, __half, wmma::row_major> AFragH;
typedef wmma::fragment<wmma::matrix_b, 16, 16, 16, __half, wmma::col_major> BFragHC;
typedef wmma::fragment<wmma::matrix_b, 16, 16, 16, __half, wmma::row_major> BFragHR;
typedef wmma::fragment<wmma::accumulator, 16, 16, 16, float> CFragH;

// ============================================================
// casgemm (R9/R10-proven): 128x128 tile, 256 thr, BK=64,
// 3 stages, 2 CTA/SM.  EPI: 0 none, 1 +bias, 2 +res, 3 silu.
// ============================================================
#define BKC 64
#define CPITCH 72
#define CSTAGE (128 * CPITCH)
#define CAS_SMEM_BYTES (3 * 2 * CSTAGE * 2)

template <int EPI, int HOUT>
__global__ void __launch_bounds__(256, 2)
casgemm_tn(const __half* __restrict__ A, int lda,
           const __half* __restrict__ B, int ldb,
           void* __restrict__ Cv, int ldc, int K,
           const float* __restrict__ bias,
           const float* __restrict__ res,
           const __half* __restrict__ resH)
{
    extern __shared__ __half csmem[];
    const uint32_t sm32 = (uint32_t)__cvta_generic_to_shared(csmem);

    const int tid  = threadIdx.x;
    const int wid  = tid >> 5;
    const int lane = tid & 31;
    const int m0 = blockIdx.y * 128;
    const int n0 = blockIdx.x * 128;
    const int wm = wid & 1, wn = wid >> 1;

    CFragH c[4][2];
#pragma unroll
    for (int i = 0; i < 4; i++)
#pragma unroll
        for (int j = 0; j < 2; j++) wmma::fill_fragment(c[i][j], 0.f);

    const int row = tid >> 1;
    const int cb  = (tid & 1) << 5;
    const __half* gA = A + (size_t)(m0 + row) * lda + cb;
    const __half* gB = B + (size_t)(n0 + row) * ldb + cb;
    const uint32_t tA = sm32 + (uint32_t)(row * CPITCH + cb) * 2u;
    const uint32_t tB = tA + (uint32_t)CSTAGE * 2u;

#define CAS_LOAD(slot, k0) do {                                         \
        const uint32_t _o = (uint32_t)(slot) * (2u * CSTAGE * 2u);      \
        _Pragma("unroll")                                               \
        for (int _u = 0; _u < 4; _u++) {                                \
            cp16(tA + _o + _u * 16u, gA + (k0) + _u * 8);               \
            cp16(tB + _o + _u * 16u, gB + (k0) + _u * 8);               \
        }                                                               \
    } while (0)

    const int nt = K / BKC;

    CAS_LOAD(0, 0);      cp_commit();
    CAS_LOAD(1, BKC);    cp_commit();

    for (int t = 0; t < nt; t++) {
        cp_wait<1>();
        __syncthreads();
        if (t + 2 < nt) CAS_LOAD((t + 2) % 3, (t + 2) * BKC);
        cp_commit();

        const __half* sA = csmem + (t % 3) * 2 * CSTAGE;
        const __half* sB = sA + CSTAGE;
#pragma unroll
        for (int ks = 0; ks < BKC; ks += 16) {
            AFragH af[4];
            BFragHC bf[2];
#pragma unroll
            for (int i = 0; i < 4; i++)
                wmma::load_matrix_sync(af[i], sA + (wm * 64 + i * 16) * CPITCH + ks, CPITCH);
#pragma unroll
            for (int j = 0; j < 2; j++)
                wmma::load_matrix_sync(bf[j], sB + (wn * 32 + j * 16) * CPITCH + ks, CPITCH);
#pragma unroll
            for (int i = 0; i < 4; i++)
#pragma unroll
                for (int j = 0; j < 2; j++)
                    wmma::mma_sync(c[i][j], af[i], bf[j], c[i][j]);
        }
    }
    __syncthreads();

    float* stage = reinterpret_cast<float*>(csmem) + wid * 256;
    const int r  = lane >> 1;
    const int cq = (lane & 1) << 3;
#pragma unroll
    for (int i = 0; i < 4; i++) {
#pragma unroll
        for (int j = 0; j < 2; j++) {
            wmma::store_matrix_sync(stage, c[i][j], 16, wmma::mem_row_major);
            __syncwarp();
            const size_t row_g = (size_t)(m0 + wm * 64 + i * 16 + r);
            const size_t col_g = (size_t)(n0 + wn * 32 + j * 16 + cq);
            float4 v0 = *(float4*)&stage[r * 16 + cq];
            float4 v1 = *(float4*)&stage[r * 16 + cq + 4];
            if (EPI == 1) {
                float4 b0 = *(const float4*)&bias[col_g];
                float4 b1 = *(const float4*)&bias[col_g + 4];
                v0.x += b0.x; v0.y += b0.y; v0.z += b0.z; v0.w += b0.w;
                v1.x += b1.x; v1.y += b1.y; v1.z += b1.z; v1.w += b1.w;
            }
            if (EPI == 2) {
                float4 r0 = *(const float4*)&res[row_g * ldc + col_g];
                float4 r1 = *(const float4*)&res[row_g * ldc + col_g + 4];
                v0.x += r0.x; v0.y += r0.y; v0.z += r0.z; v0.w += r0.w;
                v1.x += r1.x; v1.y += r1.y; v1.z += r1.z; v1.w += r1.w;
            }
            if (EPI == 3) {
                uint4 gu = *(const uint4*)&resH[row_g * ldc + col_g];
                __half2* gh = (__half2*)&gu;
                float2 g0 = __half22float2(gh[0]);
                float2 g1 = __half22float2(gh[1]);
                float2 g2 = __half22float2(gh[2]);
                float2 g3 = __half22float2(gh[3]);
                v0.x *= g0.x / (1.f + expf(-g0.x));
                v0.y *= g0.y / (1.f + expf(-g0.y));
                v0.z *= g1.x / (1.f + expf(-g1.x));
                v0.w *= g1.y / (1.f + expf(-g1.y));
                v1.x *= g2.x / (1.f + expf(-g2.x));
                v1.y *= g2.y / (1.f + expf(-g2.y));
                v1.z *= g3.x / (1.f + expf(-g3.x));
                v1.w *= g3.y / (1.f + expf(-g3.y));
            }
            if (HOUT) {
                __half* C = (__half*)Cv;
                __half2 h[4];
                h[0] = __floats2half2_rn(v0.x, v0.y);
                h[1] = __floats2half2_rn(v0.z, v0.w);
                h[2] = __floats2half2_rn(v1.x, v1.y);
                h[3] = __floats2half2_rn(v1.z, v1.w);
                *(uint4*)&C[row_g * ldc + col_g] = *(uint4*)h;
            } else {
                float* C = (float*)Cv;
                *(float4*)&C[row_g * ldc + col_g] = v0;
                *(float4*)&C[row_g * ldc + col_g + 4] = v1;
            }
            __syncwarp();
        }
    }
#undef CAS_LOAD
}

// ============================================================
// PV cp.async (R10-proven) + heavy-first tile order
// ============================================================
#define PV_APITCH 72
#define PV_ASTAGE (128 * PV_APITCH)
#define PV_BPITCH 136
#define PV_BSTAGE (64 * PV_BPITCH)
#define PV_SLOT   (PV_ASTAGE + PV_BSTAGE)
#define PV_SMEM_BYTES (3 * PV_SLOT * 2)

__global__ void __launch_bounds__(256, 2)
hpv_cas(const __half* __restrict__ p, const __half* __restrict__ v, int ldv,
        __half* __restrict__ out)
{
    extern __shared__ __half csmem[];
    const uint32_t sm32 = (uint32_t)__cvta_generic_to_shared(csmem);

    const int z = blockIdx.z;
    const int b = z / NH, h = z % NH, kvh = h / GRP;
    const int m0 = (gridDim.y - 1 - blockIdx.y) * 128;   // heavy tiles first
    const __half* A = p + (size_t)z * SEQ * SEQ;
    const __half* B = v + (size_t)b * SEQ * ldv + (size_t)kvh * HD;
    __half* C = out + (size_t)b * SEQ * HIDN + (size_t)h * HD;

    const int tid  = threadIdx.x;
    const int wid  = tid >> 5;
    const int lane = tid & 31;
    const int wm = wid & 1, wn = wid >> 1;

    CFragH c[4][2];
#pragma unroll
    for (int i = 0; i < 4; i++)
#pragma unroll
        for (int j = 0; j < 2; j++) wmma::fill_fragment(c[i][j], 0.f);

    const int arow = tid >> 1;
    const int acb  = (tid & 1) << 5;
    const int brow = tid >> 2;
    const int bcb  = (tid & 3) << 5;
    const __half* gA = A + (size_t)(m0 + arow) * SEQ + acb;
    const uint32_t tA = sm32 + (uint32_t)(arow * PV_APITCH + acb) * 2u;
    const uint32_t tB = sm32 + (uint32_t)(PV_ASTAGE + brow * PV_BPITCH + bcb) * 2u;

#define PV_LOAD(slot, k0) do {                                          \
        const uint32_t _o = (uint32_t)(slot) * (PV_SLOT * 2u);          \
        const __half* _gb = B + (size_t)((k0) + brow) * ldv + bcb;      \
        _Pragma("unroll")                                               \
        for (int _u = 0; _u < 4; _u++) {                                \
            cp16(tA + _o + _u * 16u, gA + (k0) + _u * 8);               \
            cp16(tB + _o + _u * 16u, _gb + _u * 8);                     \
        }                                                               \
    } while (0)

    const int nt = (m0 + 128) / BKC;

    PV_LOAD(0, 0);    cp_commit();
    PV_LOAD(1, BKC);  cp_commit();

    for (int t = 0; t < nt; t++) {
        cp_wait<1>();
        __syncthreads();
        if (t + 2 < nt) PV_LOAD((t + 2) % 3, (t + 2) * BKC);
        cp_commit();

        const __half* sA = csmem + (t % 3) * PV_SLOT;
        const __half* sB = sA + PV_ASTAGE;
#pragma unroll
        for (int ks = 0; ks < BKC; ks += 16) {
            AFragH af[4];
            BFragHR bf[2];
#pragma unroll
            for (int i = 0; i < 4; i++)
                wmma::load_matrix_sync(af[i], sA + (wm * 64 + i * 16) * PV_APITCH + ks, PV_APITCH);
#pragma unroll
            for (int j = 0; j < 2; j++)
                wmma::load_matrix_sync(bf[j], sB + ks * PV_BPITCH + (wn * 32 + j * 16), PV_BPITCH);
#pragma unroll
            for (int i = 0; i < 4; i++)
#pragma unroll
                for (int j = 0; j < 2; j++)
                    wmma::mma_sync(c[i][j], af[i], bf[j], c[i][j]);
        }
    }
    __syncthreads();

    float* stage = reinterpret_cast<float*>(csmem) + wid * 256;
    const int r  = lane >> 1;
    const int cq = (lane & 1) << 3;
#pragma unroll
    for (int i = 0; i < 4; i++) {
#pragma unroll
        for (int j = 0; j < 2; j++) {
            wmma::store_matrix_sync(stage, c[i][j], 16, wmma::mem_row_major);
            __syncwarp();
            const size_t row_g = (size_t)(m0 + wm * 64 + i * 16 + r);
            const size_t col_g = (size_t)(wn * 32 + j * 16 + cq);
            float4 v0 = *(float4*)&stage[r * 16 + cq];
            float4 v1 = *(float4*)&stage[r * 16 + cq + 4];
            __half2 hh[4];
            hh[0] = __floats2half2_rn(v0.x, v0.y);
            hh[1] = __floats2half2_rn(v0.z, v0.w);
            hh[2] = __floats2half2_rn(v1.x, v1.y);
            hh[3] = __floats2half2_rn(v1.z, v1.w);
            *(uint4*)&C[row_g * HIDN + col_g] = *(uint4*)hh;
            __syncwarp();
        }
    }
#undef PV_LOAD
}

// ============================================================
// Scores -> fp16 (R13-proven)
// ============================================================
#define BM 128
#define BN 128
#define BK 32
#define HPITCH 40
#define HSTAGE (128 * HPITCH)

__global__ void __launch_bounds__(256, 2)
hscores(const __half* __restrict__ q, const __half* __restrict__ k,
        __half* __restrict__ scores)
{
    if (blockIdx.x > blockIdx.y) return;

    const int z = blockIdx.z;
    const int b = z / NH, h = z % NH, kvh = h / GRP;
    const int m0 = blockIdx.y * BM;
    const int n0 = blockIdx.x * BN;
    const __half* A = q + (size_t)b * SEQ * HIDN + (size_t)h * HD;
    const __half* B = k + (size_t)b * SEQ * KVW + (size_t)kvh * HD;
    __half* C = scores + (size_t)z * SEQ * SEQ;
    const bool diag = (blockIdx.x == blockIdx.y);

    __shared__ __align__(16) __half smem[4 * HSTAGE];
    __half* sA[2] = { smem,              smem + HSTAGE };
    __half* sB[2] = { smem + 2 * HSTAGE, smem + 3 * HSTAGE };

    const int tid  = threadIdx.x;
    const int wid  = tid >> 5;
    const int lane = tid & 31;
    const int wm = wid & 1, wn = wid >> 1;

    CFragH c[4][2];
#pragma unroll
    for (int i = 0; i < 4; i++)
#pragma unroll
        for (int jj = 0; jj < 2; jj++) wmma::fill_fragment(c[i][jj], 0.f);

    const int row = tid >> 1;
    const int c0  = (tid & 1) << 4;
    const __half* gA = A + (size_t)(m0 + row) * HIDN + c0;
    const __half* gB = B + (size_t)(n0 + row) * KVW + c0;

    uint4 ra0, ra1, rb0, rb1;
    ra0 = *(const uint4*)(gA);
    ra1 = *(const uint4*)(gA + 8);
    rb0 = *(const uint4*)(gB);
    rb1 = *(const uint4*)(gB + 8);
    {
        __half* a = sA[0] + row * HPITCH + c0;
        *(uint4*)a = ra0; *(uint4*)(a + 8) = ra1;
        __half* bb = sB[0] + row * HPITCH + c0;
        *(uint4*)bb = rb0; *(uint4*)(bb + 8) = rb1;
    }
    __syncthreads();

    const int nt = HD / BK;
    for (int t = 0; t < nt; t++) {
        const int cur = t & 1;
        if (t + 1 < nt) {
            const int k0 = (t + 1) * BK;
            ra0 = *(const uint4*)(gA + k0);
            ra1 = *(const uint4*)(gA + k0 + 8);
            rb0 = *(const uint4*)(gB + k0);
            rb1 = *(const uint4*)(gB + k0 + 8);
        }
#pragma unroll
        for (int ks = 0; ks < BK; ks += 16) {
            AFragH af[4];
            BFragHC bf[2];
#pragma unroll
            for (int i = 0; i < 4; i++)
                wmma::load_matrix_sync(af[i], sA[cur] + (wm * 64 + i * 16) * HPITCH + ks, HPITCH);
#pragma unroll
            for (int jj = 0; jj < 2; jj++)
                wmma::load_matrix_sync(bf[jj], sB[cur] + (wn * 32 + jj * 16) * HPITCH + ks, HPITCH);
#pragma unroll
            for (int i = 0; i < 4; i++)
#pragma unroll
                for (int jj = 0; jj < 2; jj++)
                    wmma::mma_sync(c[i][jj], af[i], bf[jj], c[i][jj]);
        }
        if (t + 1 < nt) {
            const int nxt = cur ^ 1;
            __half* a = sA[nxt] + row * HPITCH + c0;
            *(uint4*)a = ra0; *(uint4*)(a + 8) = ra1;
            __half* bb = sB[nxt] + row * HPITCH + c0;
            *(uint4*)bb = rb0; *(uint4*)(bb + 8) = rb1;
        }
        __syncthreads();
    }

    float* stage = reinterpret_cast<float*>(smem) + wid * 256;
    const int r  = lane >> 1;
    const int cq = (lane & 1) << 3;
#pragma unroll
    for (int i = 0; i < 4; i++) {
#pragma unroll
        for (int jj = 0; jj < 2; jj++) {
            wmma::store_matrix_sync(stage, c[i][jj], 16, wmma::mem_row_major);
            __syncwarp();
            const size_t row_g = (size_t)(m0 + wm * 64 + i * 16 + r);
            const size_t col_g = (size_t)(n0 + wn * 32 + jj * 16 + cq);
            float4 v0 = *(float4*)&stage[r * 16 + cq];
            float4 v1 = *(float4*)&stage[r * 16 + cq + 4];
            if (diag) {
                if (col_g + 0 > row_g) v0.x = NEG16;
                if (col_g + 1 > row_g) v0.y = NEG16;
                if (col_g + 2 > row_g) v0.z = NEG16;
                if (col_g + 3 > row_g) v0.w = NEG16;
                if (col_g + 4 > row_g) v1.x = NEG16;
                if (col_g + 5 > row_g) v1.y = NEG16;
                if (col_g + 6 > row_g) v1.z = NEG16;
                if (col_g + 7 > row_g) v1.w = NEG16;
            }
            __half2 hh[4];
            hh[0] = __floats2half2_rn(v0.x, v0.y);
            hh[1] = __floats2half2_rn(v0.z, v0.w);
            hh[2] = __floats2half2_rn(v1.x, v1.y);
            hh[3] = __floats2half2_rn(v1.z, v1.w);
            *(uint4*)&C[row_g * SEQ + col_g] = *(uint4*)hh;
            __syncwarp();
        }
    }
}

// ---------------- elementwise / reduction kernels ----------------

// fp32->fp16: 8 floats/thread, 2x LDG.128 + 1x STG.128
__global__ void __launch_bounds__(256)
f2h_kernel(const float* __restrict__ in, __half* __restrict__ out, int n)
{
    int i = (blockIdx.x * blockDim.x + threadIdx.x) * 8;
    int stride = gridDim.x * blockDim.x * 8;
    for (; i < n; i += stride) {
        float4 v0 = *(const float4*)(in + i);
        float4 v1 = *(const float4*)(in + i + 4);
        __half2 h[4];
        h[0] = __floats2half2_rn(v0.x, v0.y);
        h[1] = __floats2half2_rn(v0.z, v0.w);
        h[2] = __floats2half2_rn(v1.x, v1.y);
        h[3] = __floats2half2_rn(v1.z, v1.w);
        *(uint4*)(out + i) = *(uint4*)h;
    }
}

__global__ void __launch_bounds__(256)
bias_concat_kernel(const float* __restrict__ bq, const float* __restrict__ bk,
                   const float* __restrict__ bv, float* __restrict__ dst)
{
    int i = blockIdx.x * blockDim.x + threadIdx.x;
    if (i < HIDN) dst[i] = bq[i];
    else if (i < HIDN + KVW) dst[i] = bk[i - HIDN];
    else if (i < NQKV) dst[i] = bv[i - HIDN - KVW];
}

// length-aware softmax, fp16 in place, vectorized (8 halves/thread)
__global__ void __launch_bounds__(128)
softmax_kernel(__half* __restrict__ s)
{
    const size_t base = (size_t)blockIdx.x * SEQ;
    const int r = blockIdx.x & (SEQ - 1);
    const int L = ((r >> 7) + 1) << 7;
    const int tid = threadIdx.x;
    const int idx = tid * 8;
    const bool act = idx < L;
    __shared__ float red[4];

    float f[8];
    float mx = -1e30f;
    if (act) {
        uint4 u = *(uint4*)&s[base + idx];
        __half2* hp = (__half2*)&u;
#pragma unroll
        for (int j = 0; j < 4; j++) {
            float2 p = __half22float2(hp[j]);
            f[j * 2]     = p.x;
            f[j * 2 + 1] = p.y;
            mx = fmaxf(mx, fmaxf(p.x, p.y));
        }
    }
#pragma unroll
    for (int o = 16; o > 0; o >>= 1) mx = fmaxf(mx, __shfl_xor_sync(0xffffffffu, mx, o));
    if ((tid & 31) == 0) red[tid >> 5] = mx;
    __syncthreads();
    float m2 = fmaxf(fmaxf(red[0], red[1]), fmaxf(red[2], red[3]));
    __syncthreads();

    float sum = 0.f;
    if (act) {
#pragma unroll
        for (int j = 0; j < 8; j++) {
            f[j] = expf(f[j] - m2);
            sum += f[j];
        }
    }
#pragma unroll
    for (int o = 16; o > 0; o >>= 1) sum += __shfl_xor_sync(0xffffffffu, sum, o);
    if ((tid & 31) == 0) red[tid >> 5] = sum;
    __syncthreads();
    float inv = 1.f / (red[0] + red[1] + red[2] + red[3]);

    if (act) {
        __half2 h[4];
#pragma unroll
        for (int j = 0; j < 4; j++)
            h[j] = __floats2half2_rn(f[j * 2] * inv, f[j * 2 + 1] * inv);
        *(uint4*)&s[base + idx] = *(uint4*)h;
    }
}

__global__ void __launch_bounds__(256)
rmsnorm_h_kernel(const float* __restrict__ x, const float* __restrict__ w,
                 __half* __restrict__ out)
{
    const size_t base = (size_t)blockIdx.x * HIDN;
    const int tid = threadIdx.x;
    __shared__ float red[8];

    float v[8];
    float ss = 0.f;
#pragma unroll
    for (int jj = 0; jj < 8; jj++) {
        v[jj] = x[base + tid + jj * 256];
        ss += v[jj] * v[jj];
    }
#pragma unroll
    for (int o = 16; o > 0; o >>= 1) ss += __shfl_xor_sync(0xffffffffu, ss, o);
    if ((tid & 31) == 0) red[tid >> 5] = ss;
    __syncthreads();
    float tot = red[0] + red[1] + red[2] + red[3] + red[4] + red[5] + red[6] + red[7];
    float r = rsqrtf(tot * (1.f / HIDN) + EPSV);
#pragma unroll
    for (int jj = 0; jj < 8; jj++)
        out[base + tid + jj * 256] = __float2half_rn(v[jj] * r * w[tid + jj * 256]);
}

__global__ void __launch_bounds__(128)
head_rms_rope_h_kernel(const __half* __restrict__ buf, int instride, int inoff,
                       const float* __restrict__ w,
                       const float* __restrict__ cs, const float* __restrict__ sn,
                       __half* __restrict__ out16, int outstride, float outscale)
{
    const int t = blockIdx.x;
    const int h = blockIdx.y;
    const int i = threadIdx.x;
    const size_t iidx = (size_t)t * instride + inoff + h * HD + i;
    const size_t oidx = (size_t)t * outstride + h * HD + i;

    float v = __half2float(buf[iidx]);
    float ss = v * v;
#pragma unroll
    for (int o = 16; o > 0; o >>= 1) ss += __shfl_xor_sync(0xffffffffu, ss, o);
    __shared__ float red[4];
    if ((i & 31) == 0) red[i >> 5] = ss;
    __syncthreads();
    float tot = red[0] + red[1] + red[2] + red[3];
    float n = v * rsqrtf(tot * (1.f / HD) + EPSV) * w[i];

    __shared__ float sm[HD];
    sm[i] = n;
    __syncthreads();
    float rot = (i < 64) ? -sm[i + 64] : sm[i - 64];
    float r = (n * cs[(size_t)t * HD + i] + rot * sn[(size_t)t * HD + i]) * outscale;
    out16[oidx] = __float2half_rn(r);
}

extern "C" void kernel_launch(void* const* d_in, const int* in_sizes, int n_in,
                              void* d_out, int out_size)
{
    const float* x    = (const float*)d_in[0];
    const float* cosv = (const float*)d_in[1];
    const float* sinv = (const float*)d_in[2];
    const float* wq   = (const float*)d_in[4];
    const float* bq   = (const float*)d_in[5];
    const float* wk   = (const float*)d_in[6];
    const float* bk   = (const float*)d_in[7];
    const float* wv   = (const float*)d_in[8];
    const float* bv   = (const float*)d_in[9];
    const float* wo   = (const float*)d_in[10];
    const float* qw   = (const float*)d_in[11];
    const float* kw   = (const float*)d_in[12];
    const float* ln1  = (const float*)d_in[13];
    const float* ln2  = (const float*)d_in[14];
    const float* wg   = (const float*)d_in[15];
    const float* wu   = (const float*)d_in[16];
    const float* wd   = (const float*)d_in[17];
    float* out = (float*)d_out;

    float* s = nullptr;
    cudaGetSymbolAddress((void**)&s, g_scratch);
    __half* hs = nullptr;
    cudaGetSymbolAddress((void**)&hs, g_hscratch);

    float* x2     = s + OFF_X2;
    float* biasc  = s + OFF_BIAS;

    __half* hwqkv  = hs + HW_QKV;
    __half* hwo    = hs + HW_O;
    __half* hwg    = hs + HW_G;
    __half* hwu    = hs + HW_U;
    __half* hwd    = hs + HW_D;
    __half* h16    = hs + H_H16;
    __half* qkv16  = hs + H_QKV16;
    __half* q16    = hs + H_Q16;
    __half* k16    = hs + H_K16;
    __half* p16    = hs + H_P16;
    __half* at16   = hs + H_ATTN16;
    __half* g16    = hs + H_G16;

    cudaFuncSetAttribute(casgemm_tn<1, 1>, cudaFuncAttributeMaxDynamicSharedMemorySize, CAS_SMEM_BYTES);
    cudaFuncSetAttribute(casgemm_tn<2, 0>, cudaFuncAttributeMaxDynamicSharedMemorySize, CAS_SMEM_BYTES);
    cudaFuncSetAttribute(casgemm_tn<0, 1>, cudaFuncAttributeMaxDynamicSharedMemorySize, CAS_SMEM_BYTES);
    cudaFuncSetAttribute(casgemm_tn<3, 1>, cudaFuncAttributeMaxDynamicSharedMemorySize, CAS_SMEM_BYTES);
    cudaFuncSetAttribute(hpv_cas,          cudaFuncAttributeMaxDynamicSharedMemorySize, PV_SMEM_BYTES);

    // 0. weights fp32 -> fp16 (8 floats/thread, 16B stores)
    f2h_kernel<<<2048, 256>>>(wq, hwqkv,                       HIDN * HIDN);
    f2h_kernel<<<512,  256>>>(wk, hwqkv + HIDN * HIDN,         KVW * HIDN);
    f2h_kernel<<<512,  256>>>(wv, hwqkv + (HIDN + KVW) * HIDN, KVW * HIDN);
    f2h_kernel<<<2048, 256>>>(wo, hwo, HIDN * HIDN);
    f2h_kernel<<<4096, 256>>>(wg, hwg, FF * HIDN);
    f2h_kernel<<<4096, 256>>>(wu, hwu, FF * HIDN);
    f2h_kernel<<<4096, 256>>>(wd, hwd, HIDN * FF);
    bias_concat_kernel<<<12, 256>>>(bq, bk, bv, biasc);

    // 1. h16 = rmsnorm(x, ln1)
    rmsnorm_h_kernel<<<T_TOK, 256>>>(x, ln1, h16);

    // 2. fused QKV projection (+bias) -> fp16 qkv16
    casgemm_tn<1, 1><<<dim3(NQKV / 128, T_TOK / 128), 256, CAS_SMEM_BYTES>>>(
        h16, HIDN, hwqkv, HIDN, qkv16, NQKV, HIDN, biasc, nullptr, nullptr);

    // 3-4. per-head RMS + RoPE -> q16 (pre-scaled) / k16 ; V stays in qkv16
    head_rms_rope_h_kernel<<<dim3(T_TOK, NH),  HD>>>(qkv16, NQKV, 0,    qw, cosv, sinv, q16, HIDN, SCALE);
    head_rms_rope_h_kernel<<<dim3(T_TOK, NKV), HD>>>(qkv16, NQKV, HIDN, kw, cosv, sinv, k16, KVW, 1.0f);

    // 5. scores -> fp16 p16 (lower triangle, analytic mask)
    hscores<<<dim3(SEQ / BN, SEQ / BM, BATCH * NH), 256>>>(q16, k16, p16);

    // 6. softmax in place (vectorized)
    softmax_kernel<<<BATCH * NH * SEQ, 128>>>(p16);

    // 7. attn16 = P @ V (cp.async, heavy-first; V in-place in qkv16)
    hpv_cas<<<dim3(1, SEQ / 128, BATCH * NH), 256, PV_SMEM_BYTES>>>(
        p16, qkv16 + HIDN + KVW, NQKV, at16);

    // 8. x2 = x + attn @ wo^T
    casgemm_tn<2, 0><<<dim3(HIDN / 128, T_TOK / 128), 256, CAS_SMEM_BYTES>>>(
        at16, HIDN, hwo, HIDN, x2, HIDN, HIDN, nullptr, x, nullptr);

    // 9. h16 = rmsnorm(x2, ln2)
    rmsnorm_h_kernel<<<T_TOK, 256>>>(x2, ln2, h16);

    // 10. gate -> g16 (fp16)
    casgemm_tn<0, 1><<<dim3(FF / 128, T_TOK / 128), 256, CAS_SMEM_BYTES>>>(
        h16, HIDN, hwg, HIDN, g16, FF, HIDN, nullptr, nullptr, nullptr);

    // 11. up + fused silu: g16 = silu(g16) * up (in place)
    casgemm_tn<3, 1><<<dim3(FF / 128, T_TOK / 128), 256, CAS_SMEM_BYTES>>>(
        h16, HIDN, hwu, HIDN, g16, FF, HIDN, nullptr, nullptr, g16);

    // 12. out = x2 + g16 @ wd^T
    casgemm_tn<2, 0><<<dim3(HIDN / 128, T_TOK / 128), 256, CAS_SMEM_BYTES>>>(
        g16, FF, hwd, FF, out, HIDN, FF, nullptr, x2, nullptr);
}

// round 15
// speedup vs baseline: 1.1008x; 1.0071x over previous
#include <cuda_runtime.h>
#include <cuda_fp16.h>
#include <mma.h>
#include <math.h>
#include <stdint.h>

using namespace nvcuda;

// ---------------- problem constants ----------------
#define T_TOK 4096
#define HIDN  2048
#define NH    16
#define NKV   4
#define HD    128
#define FF    8192
#define BATCH 4
#define SEQ   1024
#define GRP   (NH / NKV)
#define KVW   (NKV * HD)          // 512
#define NQKV  (HIDN + 2 * KVW)    // 3072
#define EPSV  1e-6f
#define SCALE 0.08838834764831845f
#define NEG16 -60000.0f

// ---------------- fp32 scratch ----------------
#define OFF_X2     ((size_t)0)
#define OFF_BIAS   ((size_t)8388608)
#define SCRATCH_FLOATS ((size_t)8392704)
__device__ float g_scratch[SCRATCH_FLOATS];

// ---------------- fp16 scratch ----------------
#define HW_QKV   ((size_t)0)
#define HW_O     ((size_t)6291456)
#define HW_G     ((size_t)10485760)
#define HW_U     ((size_t)27262976)
#define HW_D     ((size_t)44040192)
#define H_H16    ((size_t)60817408)
#define H_QKV16  ((size_t)69206016)
#define H_Q16    ((size_t)81788928)
#define H_K16    ((size_t)90177536)
#define H_P16    ((size_t)92274688)
#define H_ATTN16 ((size_t)159383552)
#define H_G16    ((size_t)167772160)
#define HSCRATCH_HALVES ((size_t)201326592)
__device__ __half g_hscratch[HSCRATCH_HALVES];

// ---------------- cp.async helpers ----------------
__device__ __forceinline__ void cp16(uint32_t dst, const void* src) {
    asm volatile("cp.async.cg.shared.global [%0], [%1], 16;" :: "r"(dst), "l"(src));
}
__device__ __forceinline__ void cp_commit() {
    asm volatile("cp.async.commit_group;");
}
template <int N>
__device__ __forceinline__ void cp_wait() {
    asm volatile("cp.async.wait_group %0;" :: "n"(N));
}

typedef wmma::fragment<wmma::matrix_a, 16, 16, 16, __half, wmma::row_major> AFragH;
typedef wmma::fragment<wmma::matrix_b, 16, 16, 16, __half, wmma::col_major> BFragHC;
typedef wmma::fragment<wmma::matrix_b, 16, 16, 16, __half, wmma::row_major> BFragHR;
typedef wmma::fragment<wmma::accumulator, 16, 16, 16, float> CFragH;

// ============================================================
// casgemm (R9/R10-proven): 128x128 tile, 256 thr, BK=64,
// 3 stages, 2 CTA/SM.  EPI: 0 none, 1 +bias, 2 +res, 3 silu.
// ============================================================
#define BKC 64
#define CPITCH 72
#define CSTAGE (128 * CPITCH)
#define CAS_SMEM_BYTES (3 * 2 * CSTAGE * 2)

template <int EPI, int HOUT>
__global__ void __launch_bounds__(256, 2)
casgemm_tn(const __half* __restrict__ A, int lda,
           const __half* __restrict__ B, int ldb,
           void* __restrict__ Cv, int ldc, int K,
           const float* __restrict__ bias,
           const float* __restrict__ res,
           const __half* __restrict__ resH)
{
    extern __shared__ __half csmem[];
    const uint32_t sm32 = (uint32_t)__cvta_generic_to_shared(csmem);

    const int tid  = threadIdx.x;
    const int wid  = tid >> 5;
    const int lane = tid & 31;
    const int m0 = blockIdx.y * 128;
    const int n0 = blockIdx.x * 128;
    const int wm = wid & 1, wn = wid >> 1;

    CFragH c[4][2];
#pragma unroll
    for (int i = 0; i < 4; i++)
#pragma unroll
        for (int j = 0; j < 2; j++) wmma::fill_fragment(c[i][j], 0.f);

    const int row = tid >> 1;
    const int cb  = (tid & 1) << 5;
    const __half* gA = A + (size_t)(m0 + row) * lda + cb;
    const __half* gB = B + (size_t)(n0 + row) * ldb + cb;
    const uint32_t tA = sm32 + (uint32_t)(row * CPITCH + cb) * 2u;
    const uint32_t tB = tA + (uint32_t)CSTAGE * 2u;

#define CAS_LOAD(slot, k0) do {                                         \
        const uint32_t _o = (uint32_t)(slot) * (2u * CSTAGE * 2u);      \
        _Pragma("unroll")                                               \
        for (int _u = 0; _u < 4; _u++) {                                \
            cp16(tA + _o + _u * 16u, gA + (k0) + _u * 8);               \
            cp16(tB + _o + _u * 16u, gB + (k0) + _u * 8);               \
        }                                                               \
    } while (0)

    const int nt = K / BKC;

    CAS_LOAD(0, 0);      cp_commit();
    CAS_LOAD(1, BKC);    cp_commit();

    for (int t = 0; t < nt; t++) {
        cp_wait<1>();
        __syncthreads();
        if (t + 2 < nt) CAS_LOAD((t + 2) % 3, (t + 2) * BKC);
        cp_commit();

        const __half* sA = csmem + (t % 3) * 2 * CSTAGE;
        const __half* sB = sA + CSTAGE;
#pragma unroll
        for (int ks = 0; ks < BKC; ks += 16) {
            AFragH af[4];
            BFragHC bf[2];
#pragma unroll
            for (int i = 0; i < 4; i++)
                wmma::load_matrix_sync(af[i], sA + (wm * 64 + i * 16) * CPITCH + ks, CPITCH);
#pragma unroll
            for (int j = 0; j < 2; j++)
                wmma::load_matrix_sync(bf[j], sB + (wn * 32 + j * 16) * CPITCH + ks, CPITCH);
#pragma unroll
            for (int i = 0; i < 4; i++)
#pragma unroll
                for (int j = 0; j < 2; j++)
                    wmma::mma_sync(c[i][j], af[i], bf[j], c[i][j]);
        }
    }
    __syncthreads();

    float* stage = reinterpret_cast<float*>(csmem) + wid * 256;
    const int r  = lane >> 1;
    const int cq = (lane & 1) << 3;
#pragma unroll
    for (int i = 0; i < 4; i++) {
#pragma unroll
        for (int j = 0; j < 2; j++) {
            wmma::store_matrix_sync(stage, c[i][j], 16, wmma::mem_row_major);
            __syncwarp();
            const size_t row_g = (size_t)(m0 + wm * 64 + i * 16 + r);
            const size_t col_g = (size_t)(n0 + wn * 32 + j * 16 + cq);
            float4 v0 = *(float4*)&stage[r * 16 + cq];
            float4 v1 = *(float4*)&stage[r * 16 + cq + 4];
            if (EPI == 1) {
                float4 b0 = *(const float4*)&bias[col_g];
                float4 b1 = *(const float4*)&bias[col_g + 4];
                v0.x += b0.x; v0.y += b0.y; v0.z += b0.z; v0.w += b0.w;
                v1.x += b1.x; v1.y += b1.y; v1.z += b1.z; v1.w += b1.w;
            }
            if (EPI == 2) {
                float4 r0 = *(const float4*)&res[row_g * ldc + col_g];
                float4 r1 = *(const float4*)&res[row_g * ldc + col_g + 4];
                v0.x += r0.x; v0.y += r0.y; v0.z += r0.z; v0.w += r0.w;
                v1.x += r1.x; v1.y += r1.y; v1.z += r1.z; v1.w += r1.w;
            }
            if (EPI == 3) {
                uint4 gu = *(const uint4*)&resH[row_g * ldc + col_g];
                __half2* gh = (__half2*)&gu;
                float2 g0 = __half22float2(gh[0]);
                float2 g1 = __half22float2(gh[1]);
                float2 g2 = __half22float2(gh[2]);
                float2 g3 = __half22float2(gh[3]);
                v0.x *= g0.x / (1.f + expf(-g0.x));
                v0.y *= g0.y / (1.f + expf(-g0.y));
                v0.z *= g1.x / (1.f + expf(-g1.x));
                v0.w *= g1.y / (1.f + expf(-g1.y));
                v1.x *= g2.x / (1.f + expf(-g2.x));
                v1.y *= g2.y / (1.f + expf(-g2.y));
                v1.z *= g3.x / (1.f + expf(-g3.x));
                v1.w *= g3.y / (1.f + expf(-g3.y));
            }
            if (HOUT) {
                __half* C = (__half*)Cv;
                __half2 h[4];
                h[0] = __floats2half2_rn(v0.x, v0.y);
                h[1] = __floats2half2_rn(v0.z, v0.w);
                h[2] = __floats2half2_rn(v1.x, v1.y);
                h[3] = __floats2half2_rn(v1.z, v1.w);
                *(uint4*)&C[row_g * ldc + col_g] = *(uint4*)h;
            } else {
                float* C = (float*)Cv;
                *(float4*)&C[row_g * ldc + col_g] = v0;
                *(float4*)&C[row_g * ldc + col_g + 4] = v1;
            }
            __syncwarp();
        }
    }
#undef CAS_LOAD
}

// ============================================================
// PV cp.async (R14-proven, heavy-first)
// ============================================================
#define PV_APITCH 72
#define PV_ASTAGE (128 * PV_APITCH)
#define PV_BPITCH 136
#define PV_BSTAGE (64 * PV_BPITCH)
#define PV_SLOT   (PV_ASTAGE + PV_BSTAGE)
#define PV_SMEM_BYTES (3 * PV_SLOT * 2)

__global__ void __launch_bounds__(256, 2)
hpv_cas(const __half* __restrict__ p, const __half* __restrict__ v, int ldv,
        __half* __restrict__ out)
{
    extern __shared__ __half csmem[];
    const uint32_t sm32 = (uint32_t)__cvta_generic_to_shared(csmem);

    const int z = blockIdx.z;
    const int b = z / NH, h = z % NH, kvh = h / GRP;
    const int m0 = (gridDim.y - 1 - blockIdx.y) * 128;
    const __half* A = p + (size_t)z * SEQ * SEQ;
    const __half* B = v + (size_t)b * SEQ * ldv + (size_t)kvh * HD;
    __half* C = out + (size_t)b * SEQ * HIDN + (size_t)h * HD;

    const int tid  = threadIdx.x;
    const int wid  = tid >> 5;
    const int lane = tid & 31;
    const int wm = wid & 1, wn = wid >> 1;

    CFragH c[4][2];
#pragma unroll
    for (int i = 0; i < 4; i++)
#pragma unroll
        for (int j = 0; j < 2; j++) wmma::fill_fragment(c[i][j], 0.f);

    const int arow = tid >> 1;
    const int acb  = (tid & 1) << 5;
    const int brow = tid >> 2;
    const int bcb  = (tid & 3) << 5;
    const __half* gA = A + (size_t)(m0 + arow) * SEQ + acb;
    const uint32_t tA = sm32 + (uint32_t)(arow * PV_APITCH + acb) * 2u;
    const uint32_t tB = sm32 + (uint32_t)(PV_ASTAGE + brow * PV_BPITCH + bcb) * 2u;

#define PV_LOAD(slot, k0) do {                                          \
        const uint32_t _o = (uint32_t)(slot) * (PV_SLOT * 2u);          \
        const __half* _gb = B + (size_t)((k0) + brow) * ldv + bcb;      \
        _Pragma("unroll")                                               \
        for (int _u = 0; _u < 4; _u++) {                                \
            cp16(tA + _o + _u * 16u, gA + (k0) + _u * 8);               \
            cp16(tB + _o + _u * 16u, _gb + _u * 8);                     \
        }                                                               \
    } while (0)

    const int nt = (m0 + 128) / BKC;

    PV_LOAD(0, 0);    cp_commit();
    PV_LOAD(1, BKC);  cp_commit();

    for (int t = 0; t < nt; t++) {
        cp_wait<1>();
        __syncthreads();
        if (t + 2 < nt) PV_LOAD((t + 2) % 3, (t + 2) * BKC);
        cp_commit();

        const __half* sA = csmem + (t % 3) * PV_SLOT;
        const __half* sB = sA + PV_ASTAGE;
#pragma unroll
        for (int ks = 0; ks < BKC; ks += 16) {
            AFragH af[4];
            BFragHR bf[2];
#pragma unroll
            for (int i = 0; i < 4; i++)
                wmma::load_matrix_sync(af[i], sA + (wm * 64 + i * 16) * PV_APITCH + ks, PV_APITCH);
#pragma unroll
            for (int j = 0; j < 2; j++)
                wmma::load_matrix_sync(bf[j], sB + ks * PV_BPITCH + (wn * 32 + j * 16), PV_BPITCH);
#pragma unroll
            for (int i = 0; i < 4; i++)
#pragma unroll
                for (int j = 0; j < 2; j++)
                    wmma::mma_sync(c[i][j], af[i], bf[j], c[i][j]);
        }
    }
    __syncthreads();

    float* stage = reinterpret_cast<float*>(csmem) + wid * 256;
    const int r  = lane >> 1;
    const int cq = (lane & 1) << 3;
#pragma unroll
    for (int i = 0; i < 4; i++) {
#pragma unroll
        for (int j = 0; j < 2; j++) {
            wmma::store_matrix_sync(stage, c[i][j], 16, wmma::mem_row_major);
            __syncwarp();
            const size_t row_g = (size_t)(m0 + wm * 64 + i * 16 + r);
            const size_t col_g = (size_t)(wn * 32 + j * 16 + cq);
            float4 v0 = *(float4*)&stage[r * 16 + cq];
            float4 v1 = *(float4*)&stage[r * 16 + cq + 4];
            __half2 hh[4];
            hh[0] = __floats2half2_rn(v0.x, v0.y);
            hh[1] = __floats2half2_rn(v0.z, v0.w);
            hh[2] = __floats2half2_rn(v1.x, v1.y);
            hh[3] = __floats2half2_rn(v1.z, v1.w);
            *(uint4*)&C[row_g * HIDN + col_g] = *(uint4*)hh;
            __syncwarp();
        }
    }
#undef PV_LOAD
}

// ============================================================
// Scores with GQA K-reuse: one CTA per (b,kvh,mtile,ntile),
// K tile resident in smem (pitch 136), loops GRP=4 query heads.
// Writes fp16 scores into p16.
// ============================================================
#define SC_BPITCH 136
#define SC_BSZ (128 * SC_BPITCH)     // 17408 halves (full K tile)
#define SC_APITCH 40
#define SC_ASZ (128 * SC_APITCH)     // 5120 halves per A stage

__global__ void __launch_bounds__(256, 2)
hscores_g4(const __half* __restrict__ q, const __half* __restrict__ k,
           __half* __restrict__ scores)
{
    if (blockIdx.x > blockIdx.y) return;

    const int z = blockIdx.z;            // b*NKV + kvh
    const int b = z / NKV, kvh = z % NKV;
    const int m0 = blockIdx.y * 128;
    const int n0 = blockIdx.x * 128;
    const bool diag = (blockIdx.x == blockIdx.y);

    __shared__ __align__(16) __half smem[2 * SC_ASZ + SC_BSZ];  // 55296 halves
    __half* sA[2] = { smem, smem + SC_ASZ };
    __half* sB = smem + 2 * SC_ASZ;

    const int tid  = threadIdx.x;
    const int wid  = tid >> 5;
    const int lane = tid & 31;
    const int wm = wid & 1, wn = wid >> 1;

    // load full K tile once: 128 rows x 128 halves, pitch 136
    {
        const int row = tid >> 1;
        const int ch  = (tid & 1) << 6;   // 0 or 64 halves
        const __half* gB = k + (size_t)b * SEQ * KVW + (size_t)(n0 + row) * KVW
                             + (size_t)kvh * HD + ch;
        __half* d = sB + row * SC_BPITCH + ch;
#pragma unroll
        for (int u = 0; u < 8; u++)
            *(uint4*)(d + u * 8) = *(const uint4*)(gB + u * 8);
    }

    const int row = tid >> 1;
    const int c0  = (tid & 1) << 4;      // 0 or 16 halves within BK=32

#pragma unroll
    for (int g = 0; g < GRP; g++) {
        const int h = kvh * GRP + g;
        const __half* A = q + (size_t)b * SEQ * HIDN + (size_t)h * HD;
        __half* C = scores + (size_t)(((size_t)b * NH + h) * SEQ * SEQ);
        const __half* gA = A + (size_t)(m0 + row) * HIDN + c0;

        CFragH c[4][2];
#pragma unroll
        for (int i = 0; i < 4; i++)
#pragma unroll
            for (int jj = 0; jj < 2; jj++) wmma::fill_fragment(c[i][jj], 0.f);

        // prologue: A chunk 0 (BK=32)
        uint4 ra0 = *(const uint4*)(gA);
        uint4 ra1 = *(const uint4*)(gA + 8);
        {
            __half* a = sA[0] + row * SC_APITCH + c0;
            *(uint4*)a = ra0; *(uint4*)(a + 8) = ra1;
        }
        __syncthreads();   // covers B tile on g==0, A stage every g

        const int nt = HD / 32;  // 4
        for (int t = 0; t < nt; t++) {
            const int cur = t & 1;
            if (t + 1 < nt) {
                const int k0 = (t + 1) * 32;
                ra0 = *(const uint4*)(gA + k0);
                ra1 = *(const uint4*)(gA + k0 + 8);
            }
#pragma unroll
            for (int ks = 0; ks < 32; ks += 16) {
                AFragH af[4];
                BFragHC bf[2];
#pragma unroll
                for (int i = 0; i < 4; i++)
                    wmma::load_matrix_sync(af[i], sA[cur] + (wm * 64 + i * 16) * SC_APITCH + ks, SC_APITCH);
#pragma unroll
                for (int jj = 0; jj < 2; jj++)
                    wmma::load_matrix_sync(bf[jj], sB + (wn * 32 + jj * 16) * SC_BPITCH + t * 32 + ks, SC_BPITCH);
#pragma unroll
                for (int i = 0; i < 4; i++)
#pragma unroll
                    for (int jj = 0; jj < 2; jj++)
                        wmma::mma_sync(c[i][jj], af[i], bf[jj], c[i][jj]);
            }
            if (t + 1 < nt) {
                const int nxt = cur ^ 1;
                __half* a = sA[nxt] + row * SC_APITCH + c0;
                *(uint4*)a = ra0; *(uint4*)(a + 8) = ra1;
            }
            __syncthreads();
        }

        // epilogue (stage region overlaps sA; guarded by syncthreads below)
        float* stage = reinterpret_cast<float*>(smem) + wid * 256;
        const int r  = lane >> 1;
        const int cq = (lane & 1) << 3;
#pragma unroll
        for (int i = 0; i < 4; i++) {
#pragma unroll
            for (int jj = 0; jj < 2; jj++) {
                wmma::store_matrix_sync(stage, c[i][jj], 16, wmma::mem_row_major);
                __syncwarp();
                const size_t row_g = (size_t)(m0 + wm * 64 + i * 16 + r);
                const size_t col_g = (size_t)(n0 + wn * 32 + jj * 16 + cq);
                float4 v0 = *(float4*)&stage[r * 16 + cq];
                float4 v1 = *(float4*)&stage[r * 16 + cq + 4];
                if (diag) {
                    if (col_g + 0 > row_g) v0.x = NEG16;
                    if (col_g + 1 > row_g) v0.y = NEG16;
                    if (col_g + 2 > row_g) v0.z = NEG16;
                    if (col_g + 3 > row_g) v0.w = NEG16;
                    if (col_g + 4 > row_g) v1.x = NEG16;
                    if (col_g + 5 > row_g) v1.y = NEG16;
                    if (col_g + 6 > row_g) v1.z = NEG16;
                    if (col_g + 7 > row_g) v1.w = NEG16;
                }
                __half2 hh[4];
                hh[0] = __floats2half2_rn(v0.x, v0.y);
                hh[1] = __floats2half2_rn(v0.z, v0.w);
                hh[2] = __floats2half2_rn(v1.x, v1.y);
                hh[3] = __floats2half2_rn(v1.z, v1.w);
                *(uint4*)&C[row_g * SEQ + col_g] = *(uint4*)hh;
                __syncwarp();
            }
        }
        __syncthreads();   // stage region reused as sA next head
    }
}

// ---------------- elementwise / reduction kernels ----------------

__global__ void __launch_bounds__(256)
f2h_kernel(const float* __restrict__ in, __half* __restrict__ out, int n)
{
    int i = (blockIdx.x * blockDim.x + threadIdx.x) * 8;
    int stride = gridDim.x * blockDim.x * 8;
    for (; i < n; i += stride) {
        float4 v0 = *(const float4*)(in + i);
        float4 v1 = *(const float4*)(in + i + 4);
        __half2 h[4];
        h[0] = __floats2half2_rn(v0.x, v0.y);
        h[1] = __floats2half2_rn(v0.z, v0.w);
        h[2] = __floats2half2_rn(v1.x, v1.y);
        h[3] = __floats2half2_rn(v1.z, v1.w);
        *(uint4*)(out + i) = *(uint4*)h;
    }
}

__global__ void __launch_bounds__(256)
bias_concat_kernel(const float* __restrict__ bq, const float* __restrict__ bk,
                   const float* __restrict__ bv, float* __restrict__ dst)
{
    int i = blockIdx.x * blockDim.x + threadIdx.x;
    if (i < HIDN) dst[i] = bq[i];
    else if (i < HIDN + KVW) dst[i] = bk[i - HIDN];
    else if (i < NQKV) dst[i] = bv[i - HIDN - KVW];
}

// warp-per-row softmax, fp16 in place; 8 rows per 256-thr block
__global__ void __launch_bounds__(256)
softmax_kernel(__half* __restrict__ s)
{
    const int rowg = blockIdx.x * 8 + (threadIdx.x >> 5);
    const int lane = threadIdx.x & 31;
    const size_t base = (size_t)rowg * SEQ;
    const int r = rowg & (SEQ - 1);
    const int L = ((r >> 7) + 1) << 7;
    const int np = (L + 255) >> 8;       // passes of 256 halves

    float f[32];
    float mx = -1e30f;
    for (int p = 0; p < np; p++) {
        const int idx = p * 256 + lane * 8;
        if (idx < L) {
            uint4 u = *(uint4*)&s[base + idx];
            __half2* hp = (__half2*)&u;
#pragma unroll
            for (int j = 0; j < 4; j++) {
                float2 pv = __half22float2(hp[j]);
                f[p * 8 + j * 2]     = pv.x;
                f[p * 8 + j * 2 + 1] = pv.y;
                mx = fmaxf(mx, fmaxf(pv.x, pv.y));
            }
        }
    }
#pragma unroll
    for (int o = 16; o > 0; o >>= 1) mx = fmaxf(mx, __shfl_xor_sync(0xffffffffu, mx, o));

    float sum = 0.f;
    for (int p = 0; p < np; p++) {
        const int idx = p * 256 + lane * 8;
        if (idx < L) {
#pragma unroll
            for (int j = 0; j < 8; j++) {
                f[p * 8 + j] = expf(f[p * 8 + j] - mx);
                sum += f[p * 8 + j];
            }
        }
    }
#pragma unroll
    for (int o = 16; o > 0; o >>= 1) sum += __shfl_xor_sync(0xffffffffu, sum, o);
    const float inv = 1.f / sum;

    for (int p = 0; p < np; p++) {
        const int idx = p * 256 + lane * 8;
        if (idx < L) {
            __half2 h[4];
#pragma unroll
            for (int j = 0; j < 4; j++)
                h[j] = __floats2half2_rn(f[p * 8 + j * 2] * inv, f[p * 8 + j * 2 + 1] * inv);
            *(uint4*)&s[base + idx] = *(uint4*)h;
        }
    }
}

__global__ void __launch_bounds__(256)
rmsnorm_h_kernel(const float* __restrict__ x, const float* __restrict__ w,
                 __half* __restrict__ out)
{
    const size_t base = (size_t)blockIdx.x * HIDN;
    const int tid = threadIdx.x;
    __shared__ float red[8];

    float v[8];
    float ss = 0.f;
#pragma unroll
    for (int jj = 0; jj < 8; jj++) {
        v[jj] = x[base + tid + jj * 256];
        ss += v[jj] * v[jj];
    }
#pragma unroll
    for (int o = 16; o > 0; o >>= 1) ss += __shfl_xor_sync(0xffffffffu, ss, o);
    if ((tid & 31) == 0) red[tid >> 5] = ss;
    __syncthreads();
    float tot = red[0] + red[1] + red[2] + red[3] + red[4] + red[5] + red[6] + red[7];
    float r = rsqrtf(tot * (1.f / HIDN) + EPSV);
#pragma unroll
    for (int jj = 0; jj < 8; jj++)
        out[base + tid + jj * 256] = __float2half_rn(v[jj] * r * w[tid + jj * 256]);
}

__global__ void __launch_bounds__(128)
head_rms_rope_h_kernel(const __half* __restrict__ buf, int instride, int inoff,
                       const float* __restrict__ w,
                       const float* __restrict__ cs, const float* __restrict__ sn,
                       __half* __restrict__ out16, int outstride, float outscale)
{
    const int t = blockIdx.x;
    const int h = blockIdx.y;
    const int i = threadIdx.x;
    const size_t iidx = (size_t)t * instride + inoff + h * HD + i;
    const size_t oidx = (size_t)t * outstride + h * HD + i;

    float v = __half2float(buf[iidx]);
    float ss = v * v;
#pragma unroll
    for (int o = 16; o > 0; o >>= 1) ss += __shfl_xor_sync(0xffffffffu, ss, o);
    __shared__ float red[4];
    if ((i & 31) == 0) red[i >> 5] = ss;
    __syncthreads();
    float tot = red[0] + red[1] + red[2] + red[3];
    float n = v * rsqrtf(tot * (1.f / HD) + EPSV) * w[i];

    __shared__ float sm[HD];
    sm[i] = n;
    __syncthreads();
    float rot = (i < 64) ? -sm[i + 64] : sm[i - 64];
    float r = (n * cs[(size_t)t * HD + i] + rot * sn[(size_t)t * HD + i]) * outscale;
    out16[oidx] = __float2half_rn(r);
}

extern "C" void kernel_launch(void* const* d_in, const int* in_sizes, int n_in,
                              void* d_out, int out_size)
{
    const float* x    = (const float*)d_in[0];
    const float* cosv = (const float*)d_in[1];
    const float* sinv = (const float*)d_in[2];
    const float* wq   = (const float*)d_in[4];
    const float* bq   = (const float*)d_in[5];
    const float* wk   = (const float*)d_in[6];
    const float* bk   = (const float*)d_in[7];
    const float* wv   = (const float*)d_in[8];
    const float* bv   = (const float*)d_in[9];
    const float* wo   = (const float*)d_in[10];
    const float* qw   = (const float*)d_in[11];
    const float* kw   = (const float*)d_in[12];
    const float* ln1  = (const float*)d_in[13];
    const float* ln2  = (const float*)d_in[14];
    const float* wg   = (const float*)d_in[15];
    const float* wu   = (const float*)d_in[16];
    const float* wd   = (const float*)d_in[17];
    float* out = (float*)d_out;

    float* s = nullptr;
    cudaGetSymbolAddress((void**)&s, g_scratch);
    __half* hs = nullptr;
    cudaGetSymbolAddress((void**)&hs, g_hscratch);

    float* x2     = s + OFF_X2;
    float* biasc  = s + OFF_BIAS;

    __half* hwqkv  = hs + HW_QKV;
    __half* hwo    = hs + HW_O;
    __half* hwg    = hs + HW_G;
    __half* hwu    = hs + HW_U;
    __half* hwd    = hs + HW_D;
    __half* h16    = hs + H_H16;
    __half* qkv16  = hs + H_QKV16;
    __half* q16    = hs + H_Q16;
    __half* k16    = hs + H_K16;
    __half* p16    = hs + H_P16;
    __half* at16   = hs + H_ATTN16;
    __half* g16    = hs + H_G16;

    cudaFuncSetAttribute(casgemm_tn<1, 1>, cudaFuncAttributeMaxDynamicSharedMemorySize, CAS_SMEM_BYTES);
    cudaFuncSetAttribute(casgemm_tn<2, 0>, cudaFuncAttributeMaxDynamicSharedMemorySize, CAS_SMEM_BYTES);
    cudaFuncSetAttribute(casgemm_tn<0, 1>, cudaFuncAttributeMaxDynamicSharedMemorySize, CAS_SMEM_BYTES);
    cudaFuncSetAttribute(casgemm_tn<3, 1>, cudaFuncAttributeMaxDynamicSharedMemorySize, CAS_SMEM_BYTES);
    cudaFuncSetAttribute(hpv_cas,          cudaFuncAttributeMaxDynamicSharedMemorySize, PV_SMEM_BYTES);

    // 0. weights fp32 -> fp16
    f2h_kernel<<<2048, 256>>>(wq, hwqkv,                       HIDN * HIDN);
    f2h_kernel<<<512,  256>>>(wk, hwqkv + HIDN * HIDN,         KVW * HIDN);
    f2h_kernel<<<512,  256>>>(wv, hwqkv + (HIDN + KVW) * HIDN, KVW * HIDN);
    f2h_kernel<<<2048, 256>>>(wo, hwo, HIDN * HIDN);
    f2h_kernel<<<4096, 256>>>(wg, hwg, FF * HIDN);
    f2h_kernel<<<4096, 256>>>(wu, hwu, FF * HIDN);
    f2h_kernel<<<4096, 256>>>(wd, hwd, HIDN * FF);
    bias_concat_kernel<<<12, 256>>>(bq, bk, bv, biasc);

    // 1. h16 = rmsnorm(x, ln1)
    rmsnorm_h_kernel<<<T_TOK, 256>>>(x, ln1, h16);

    // 2. fused QKV projection (+bias) -> fp16 qkv16
    casgemm_tn<1, 1><<<dim3(NQKV / 128, T_TOK / 128), 256, CAS_SMEM_BYTES>>>(
        h16, HIDN, hwqkv, HIDN, qkv16, NQKV, HIDN, biasc, nullptr, nullptr);

    // 3-4. per-head RMS + RoPE -> q16 (pre-scaled) / k16 ; V stays in qkv16
    head_rms_rope_h_kernel<<<dim3(T_TOK, NH),  HD>>>(qkv16, NQKV, 0,    qw, cosv, sinv, q16, HIDN, SCALE);
    head_rms_rope_h_kernel<<<dim3(T_TOK, NKV), HD>>>(qkv16, NQKV, HIDN, kw, cosv, sinv, k16, KVW, 1.0f);

    // 5. scores -> fp16 p16 (GQA K-reuse, lower triangle, analytic mask)
    hscores_g4<<<dim3(SEQ / 128, SEQ / 128, BATCH * NKV), 256>>>(q16, k16, p16);

    // 6. softmax in place (warp-per-row)
    softmax_kernel<<<BATCH * NH * SEQ / 8, 256>>>(p16);

    // 7. attn16 = P @ V (cp.async, heavy-first; V in-place in qkv16)
    hpv_cas<<<dim3(1, SEQ / 128, BATCH * NH), 256, PV_SMEM_BYTES>>>(
        p16, qkv16 + HIDN + KVW, NQKV, at16);

    // 8. x2 = x + attn @ wo^T
    casgemm_tn<2, 0><<<dim3(HIDN / 128, T_TOK / 128), 256, CAS_SMEM_BYTES>>>(
        at16, HIDN, hwo, HIDN, x2, HIDN, HIDN, nullptr, x, nullptr);

    // 9. h16 = rmsnorm(x2, ln2)
    rmsnorm_h_kernel<<<T_TOK, 256>>>(x2, ln2, h16);

    // 10. gate -> g16 (fp16)
    casgemm_tn<0, 1><<<dim3(FF / 128, T_TOK / 128), 256, CAS_SMEM_BYTES>>>(
        h16, HIDN, hwg, HIDN, g16, FF, HIDN, nullptr, nullptr, nullptr);

    // 11. up + fused silu: g16 = silu(g16) * up (in place)
    casgemm_tn<3, 1><<<dim3(FF / 128, T_TOK / 128), 256, CAS_SMEM_BYTES>>>(
        h16, HIDN, hwu, HIDN, g16, FF, HIDN, nullptr, nullptr, g16);

    // 12. out = x2 + g16 @ wd^T
    casgemm_tn<2, 0><<<dim3(HIDN / 128, T_TOK / 128), 256, CAS_SMEM_BYTES>>>(
        g16, FF, hwd, FF, out, HIDN, FF, nullptr, x2, nullptr);
}